// round 11
// baseline (speedup 1.0000x reference)
#include <cuda_runtime.h>
#include <cuda_bf16.h>
#include <cstdint>

#define BB 4
#define CC 256
#define CQ 64
#define NN 4096

// ---------------- scratch (device globals; no allocations) ----------------
__device__ __nv_bfloat16 g_A[(size_t)BB * NN * NN];     // U = exp(E), bf16, unnormalized
__device__ __nv_bfloat16 g_xhi[(size_t)BB * CC * NN];
__device__ __nv_bfloat16 g_xlo[(size_t)BB * CC * NN];
__device__ float g_V[(size_t)BB * CC * NN];             // V fp32 (pre-rescale)
__device__ __nv_bfloat16 g_Vhi[(size_t)BB * CC * NN];   // V' = V*invrs, single bf16 plane
__device__ __nv_bfloat16 g_dhi[(size_t)BB * CC * NN];   // d = x - xr*colscale, split
__device__ __nv_bfloat16 g_dlo[(size_t)BB * CC * NN];
__device__ __nv_bfloat16 g_Qthi[(size_t)BB * NN * CQ];  // Q transposed [n][o]
__device__ __nv_bfloat16 g_Qtlo[(size_t)BB * NN * CQ];
__device__ __nv_bfloat16 g_Khi[(size_t)BB * CQ * NN];
__device__ __nv_bfloat16 g_Klo[(size_t)BB * CQ * NN];
__device__ __nv_bfloat16 g_Wqkvhi[384 * CC];            // Wq(64) ; Wk(64) ; Wv(256) rows
__device__ __nv_bfloat16 g_Wqkvlo[384 * CC];
__device__ __nv_bfloat16 g_Wthi[CC * CC];
__device__ __nv_bfloat16 g_Wtlo[CC * CC];
__device__ float g_T[(size_t)BB * CC * NN];
__device__ float g_rspart[8 * BB * NN];                 // per-colgroup rowsum partials
__device__ float g_invrs[BB * NN];                      // 1 / softmax row sums
__device__ float g_colsum[BB * NN];
__device__ float g_sum[CC];
__device__ float g_sumsq[CC];
__device__ float g_scale[CC];
__device__ float g_shift[CC];

// ---------------- PTX helpers ----------------
__device__ __forceinline__ void mma16816(float* c, const uint32_t* a, const uint32_t* b) {
    asm volatile(
        "mma.sync.aligned.m16n8k16.row.col.f32.bf16.bf16.f32 "
        "{%0,%1,%2,%3}, {%4,%5,%6,%7}, {%8,%9}, {%0,%1,%2,%3};\n"
        : "+f"(c[0]), "+f"(c[1]), "+f"(c[2]), "+f"(c[3])
        : "r"(a[0]), "r"(a[1]), "r"(a[2]), "r"(a[3]), "r"(b[0]), "r"(b[1]));
}
__device__ __forceinline__ void ldsm4(uint32_t* r, uint32_t addr) {
    asm volatile("ldmatrix.sync.aligned.m8n8.x4.shared.b16 {%0,%1,%2,%3}, [%4];"
        : "=r"(r[0]), "=r"(r[1]), "=r"(r[2]), "=r"(r[3]) : "r"(addr));
}
__device__ __forceinline__ void ldsm4t(uint32_t* r, uint32_t addr) {
    asm volatile("ldmatrix.sync.aligned.m8n8.x4.trans.shared.b16 {%0,%1,%2,%3}, [%4];"
        : "=r"(r[0]), "=r"(r[1]), "=r"(r[2]), "=r"(r[3]) : "r"(addr));
}
__device__ __forceinline__ void cpasync16(uint32_t saddr, const void* g) {
    asm volatile("cp.async.cg.shared.global [%0], [%1], 16;" :: "r"(saddr), "l"(g));
}
__device__ __forceinline__ void cp_commit() { asm volatile("cp.async.commit_group;" ::: "memory"); }

__device__ __forceinline__ void split1(float v, __nv_bfloat16& h, __nv_bfloat16& l) {
    h = __float2bfloat16(v);
    l = __float2bfloat16(v - __bfloat162float(h));
}
__device__ __forceinline__ void split_pack(float a, float b, __nv_bfloat162& hi2, __nv_bfloat162& lo2) {
    __nv_bfloat16 ha, la, hb, lb;
    split1(a, ha, la); split1(b, hb, lb);
    hi2.x = ha; hi2.y = hb;
    lo2.x = la; lo2.y = lb;
}

// ---------------- unified bf16-split tensor-core GEMM, 4-stage pipeline ----------------
// (used for QKV projection and transform; x_r has its own retiled kernel below)
#define SA_STRIDE 24
#define SB_STRIDE 136

template<int NA, int NB, int EPI>
__global__ __launch_bounds__(256)
void mma_gemm_kernel(const __nv_bfloat16* __restrict__ Ahi, const __nv_bfloat16* __restrict__ Alo,
                     int lda, size_t aBS,
                     const __nv_bfloat16* __restrict__ B0, const __nv_bfloat16* __restrict__ B1,
                     size_t bBS,
                     float* __restrict__ C, size_t cBS, int K,
                     const float* __restrict__ bias)
{
    extern __shared__ __align__(16) char dynsm[];
    constexpr uint32_t A_PLANE = 128 * SA_STRIDE * 2;          // 6144
    constexpr uint32_t B_PLANE = 16 * SB_STRIDE * 2;           // 4352
    constexpr uint32_t STAGE   = NA * A_PLANE + NB * B_PLANE;

    const int bz = blockIdx.z;
    Ahi += (size_t)bz * aBS;
    if (NA == 2) Alo += (size_t)bz * aBS;
    B0  += (size_t)bz * bBS;
    if (NB == 2) B1 += (size_t)bz * bBS;
    C += (size_t)bz * cBS;

    const int row0 = blockIdx.y * 128;
    const int col0 = blockIdx.x * 128;
    const int tid  = threadIdx.x;
    const int lane = tid & 31, warp = tid >> 5;
    const int wm = warp & 3;
    const int wn = warp >> 2;

    const int ar = tid >> 1, ac = (tid & 1) * 8;
    const int bk = tid >> 4, bc = (tid & 15) * 8;
    const size_t gA = (size_t)(row0 + ar) * lda + ac;
    const size_t gB = (size_t)bk * NN + col0 + bc;

    const uint32_t sbase = (uint32_t)__cvta_generic_to_shared(dynsm);
    const uint32_t sAst = (uint32_t)(ar * SA_STRIDE + ac) * 2;
    const uint32_t sBst = NA * A_PLANE + (uint32_t)(bk * SB_STRIDE + bc) * 2;

    float acc[2][8][4];
#pragma unroll
    for (int i = 0; i < 2; i++)
#pragma unroll
        for (int j = 0; j < 8; j++)
#pragma unroll
            for (int k = 0; k < 4; k++) acc[i][j][k] = 0.f;

    const int KT = K >> 4;

    auto issue = [&](int kt, int s) {
        const size_t ka = gA + (size_t)kt * 16;
        const size_t kb = gB + (size_t)kt * 16 * NN;
        const uint32_t st = sbase + (uint32_t)s * STAGE;
        cpasync16(st + sAst, Ahi + ka);
        if (NA == 2) cpasync16(st + A_PLANE + sAst, Alo + ka);
        cpasync16(st + sBst, B0 + kb);
        if (NB == 2) cpasync16(st + B_PLANE + sBst, B1 + kb);
    };

#pragma unroll
    for (int s = 0; s < 3; s++) { issue(s, s); cp_commit(); }

    const int lr = lane & 15, lc8 = (lane >> 4) * 8;
    const uint32_t aOff = ((wm * 32 + lr) * SA_STRIDE + lc8) * 2;
    const uint32_t bOff = NA * A_PLANE + (lr * SB_STRIDE + wn * 64 + lc8) * 2;

    for (int kt = 0; kt < KT; kt++) {
        asm volatile("cp.async.wait_group 2;" ::: "memory");
        __syncthreads();
        if (kt + 3 < KT) issue(kt + 3, (kt + 3) & 3);
        cp_commit();

        const uint32_t st = sbase + (uint32_t)(kt & 3) * STAGE;

        uint32_t ah[2][4], al[2][4];
#pragma unroll
        for (int mi = 0; mi < 2; mi++) {
            ldsm4(ah[mi], st + aOff + mi * 16 * SA_STRIDE * 2);
            if (NA == 2) ldsm4(al[mi], st + A_PLANE + aOff + mi * 16 * SA_STRIDE * 2);
        }
        uint32_t bh[4][4], bl[4][4];
#pragma unroll
        for (int j = 0; j < 4; j++) {
            ldsm4t(bh[j], st + bOff + j * 16 * 2);
            if (NB == 2) ldsm4t(bl[j], st + bOff + B_PLANE + j * 16 * 2);
        }
#pragma unroll
        for (int mi = 0; mi < 2; mi++) {
#pragma unroll
            for (int j = 0; j < 4; j++) {
                mma16816(acc[mi][2 * j],     ah[mi], &bh[j][0]);
                mma16816(acc[mi][2 * j + 1], ah[mi], &bh[j][2]);
                if (NB == 2) {
                    mma16816(acc[mi][2 * j],     ah[mi], &bl[j][0]);
                    mma16816(acc[mi][2 * j + 1], ah[mi], &bl[j][2]);
                }
                if (NA == 2) {
                    mma16816(acc[mi][2 * j],     al[mi], &bh[j][0]);
                    mma16816(acc[mi][2 * j + 1], al[mi], &bh[j][2]);
                }
            }
        }
    }

    const int gid = lane >> 2, t4 = lane & 3;

    if (EPI == 1) {
        const int by = blockIdx.y;
#pragma unroll
        for (int mi = 0; mi < 2; mi++)
#pragma unroll
            for (int nj = 0; nj < 8; nj++) {
                const int r = row0 + wm * 32 + mi * 16 + gid;
                const int col = col0 + wn * 64 + nj * 8 + t4 * 2;
                const float v00 = acc[mi][nj][0], v01 = acc[mi][nj][1];
                const float v10 = acc[mi][nj][2], v11 = acc[mi][nj][3];
                if (by == 0) {
                    if (r < 64) {  // Q -> transposed split [n][o]
                        const size_t base = (size_t)bz * NN * CQ;
                        __nv_bfloat16 h, l;
                        split1(v00, h, l); g_Qthi[base + (size_t)col * CQ + r] = h;       g_Qtlo[base + (size_t)col * CQ + r] = l;
                        split1(v01, h, l); g_Qthi[base + (size_t)(col + 1) * CQ + r] = h; g_Qtlo[base + (size_t)(col + 1) * CQ + r] = l;
                        split1(v10, h, l); g_Qthi[base + (size_t)col * CQ + r + 8] = h;       g_Qtlo[base + (size_t)col * CQ + r + 8] = l;
                        split1(v11, h, l); g_Qthi[base + (size_t)(col + 1) * CQ + r + 8] = h; g_Qtlo[base + (size_t)(col + 1) * CQ + r + 8] = l;
                    } else {       // K -> split [o][n]
                        const int kr = r - 64;
                        const size_t base = (size_t)bz * CQ * NN;
                        __nv_bfloat162 h2, l2;
                        split_pack(v00, v01, h2, l2);
                        *(__nv_bfloat162*)&g_Khi[base + (size_t)kr * NN + col] = h2;
                        *(__nv_bfloat162*)&g_Klo[base + (size_t)kr * NN + col] = l2;
                        split_pack(v10, v11, h2, l2);
                        *(__nv_bfloat162*)&g_Khi[base + (size_t)(kr + 8) * NN + col] = h2;
                        *(__nv_bfloat162*)&g_Klo[base + (size_t)(kr + 8) * NN + col] = l2;
                    }
                } else {           // V rows (+bias) -> fp32 (single rounding happens in vrescale)
                    const int vr = r - 128;
                    float* dst = g_V + (size_t)bz * CC * NN;
                    const float b0 = bias[vr], b1 = bias[vr + 8];
                    *(float2*)&dst[(size_t)vr * NN + col]       = make_float2(v00 + b0, v01 + b0);
                    *(float2*)&dst[(size_t)(vr + 8) * NN + col] = make_float2(v10 + b1, v11 + b1);
                }
            }
    }

    if (EPI == 2) {
        float ssum[2][2] = {{0.f, 0.f}, {0.f, 0.f}};
        float ssq[2][2]  = {{0.f, 0.f}, {0.f, 0.f}};
#pragma unroll
        for (int mi = 0; mi < 2; mi++)
#pragma unroll
            for (int nj = 0; nj < 8; nj++) {
                const int r = row0 + wm * 32 + mi * 16 + gid;
                const int col = col0 + wn * 64 + nj * 8 + t4 * 2;
                const float b0 = bias[r], b1 = bias[r + 8];
                const float v00 = acc[mi][nj][0] + b0, v01 = acc[mi][nj][1] + b0;
                const float v10 = acc[mi][nj][2] + b1, v11 = acc[mi][nj][3] + b1;
                *(float2*)&C[(size_t)r * NN + col]       = make_float2(v00, v01);
                *(float2*)&C[(size_t)(r + 8) * NN + col] = make_float2(v10, v11);
                ssum[mi][0] += v00 + v01;  ssq[mi][0] += v00 * v00 + v01 * v01;
                ssum[mi][1] += v10 + v11;  ssq[mi][1] += v10 * v10 + v11 * v11;
            }
#pragma unroll
        for (int mi = 0; mi < 2; mi++)
#pragma unroll
            for (int h = 0; h < 2; h++) {
                const int r = row0 + wm * 32 + mi * 16 + gid + h * 8;
                atomicAdd(&g_sum[r], ssum[mi][h]);
                atomicAdd(&g_sumsq[r], ssq[mi][h]);
            }
    }
}

// ---------------- retiled x_r GEMM: M=256 x N=64 per CTA, U read once ----------------
// xr[c,m] = sum_n V'(c,n) * U(n,m); epilogue d = x - xr*colscale -> splits
#define XA_ST 24   // halves per A row
#define XB_ST 72   // halves per B row (64 + 8 pad; conflict-free ldsm4t)

__global__ __launch_bounds__(256)
void xr_gemm_kernel(const __nv_bfloat16* __restrict__ Vp, const __nv_bfloat16* __restrict__ U,
                    const float* __restrict__ x)
{
    extern __shared__ __align__(16) char dynsm[];
    constexpr uint32_t A_PLANE = 256 * XA_ST * 2;   // 12288
    constexpr uint32_t B_PLANE = 16 * XB_ST * 2;    // 2304
    constexpr uint32_t STAGE   = A_PLANE + B_PLANE; // 14592

    const int bz = blockIdx.z;
    Vp += (size_t)bz * CC * NN;
    U  += (size_t)bz * NN * NN;
    x  += (size_t)bz * CC * NN;

    const int col0 = blockIdx.x * 64;
    const int tid  = threadIdx.x;
    const int lane = tid & 31, wm = tid >> 5;       // 8 warps, 32 rows each

    // A: 256 rows x 16 halves per chunk; 2 vectors per thread
    const int ar = tid >> 1, ac = (tid & 1) * 8;
    const size_t gA0 = (size_t)ar * NN + ac;
    const size_t gA1 = (size_t)(ar + 128) * NN + ac;
    // B: 16 rows x 64 halves; threads 0..127
    const int bkr = tid >> 3, bc = (tid & 7) * 8;
    const size_t gB = (size_t)bkr * NN + col0 + bc;

    const uint32_t sbase = (uint32_t)__cvta_generic_to_shared(dynsm);
    const uint32_t sA0 = (uint32_t)(ar * XA_ST + ac) * 2;
    const uint32_t sA1 = (uint32_t)((ar + 128) * XA_ST + ac) * 2;
    const uint32_t sB  = A_PLANE + (uint32_t)(bkr * XB_ST + bc) * 2;

    float acc[2][8][4];
#pragma unroll
    for (int i = 0; i < 2; i++)
#pragma unroll
        for (int j = 0; j < 8; j++)
#pragma unroll
            for (int k = 0; k < 4; k++) acc[i][j][k] = 0.f;

    auto issue = [&](int kt, int s) {
        const uint32_t st = sbase + (uint32_t)s * STAGE;
        const size_t ka = (size_t)kt * 16;
        cpasync16(st + sA0, Vp + gA0 + ka);
        cpasync16(st + sA1, Vp + gA1 + ka);
        if (tid < 128) cpasync16(st + sB, U + gB + (size_t)kt * 16 * NN);
    };

#pragma unroll
    for (int s = 0; s < 3; s++) { issue(s, s); cp_commit(); }

    const int lr = lane & 15, lc8 = (lane >> 4) * 8;
    const uint32_t aOff = ((wm * 32 + lr) * XA_ST + lc8) * 2;
    const uint32_t bOff = A_PLANE + (lr * XB_ST + lc8) * 2;

    for (int kt = 0; kt < 256; kt++) {
        asm volatile("cp.async.wait_group 2;" ::: "memory");
        __syncthreads();
        if (kt + 3 < 256) issue(kt + 3, (kt + 3) & 3);
        cp_commit();

        const uint32_t st = sbase + (uint32_t)(kt & 3) * STAGE;

        uint32_t ah[2][4];
#pragma unroll
        for (int mi = 0; mi < 2; mi++)
            ldsm4(ah[mi], st + aOff + mi * 16 * XA_ST * 2);
        uint32_t bh[4][4];
#pragma unroll
        for (int j = 0; j < 4; j++)
            ldsm4t(bh[j], st + bOff + j * 16 * 2);
#pragma unroll
        for (int mi = 0; mi < 2; mi++)
#pragma unroll
            for (int j = 0; j < 4; j++) {
                mma16816(acc[mi][2 * j],     ah[mi], &bh[j][0]);
                mma16816(acc[mi][2 * j + 1], ah[mi], &bh[j][2]);
            }
    }

    const int gid = lane >> 2, t4 = lane & 3;
#pragma unroll
    for (int mi = 0; mi < 2; mi++)
#pragma unroll
        for (int nj = 0; nj < 8; nj++) {
            const int r = wm * 32 + mi * 16 + gid;
            const int col = col0 + nj * 8 + t4 * 2;
            const float cs0 = 1.0f / (1e-9f + g_colsum[bz * NN + col]);
            const float cs1 = 1.0f / (1e-9f + g_colsum[bz * NN + col + 1]);
            const size_t base = (size_t)bz * CC * NN;
            const float d00 = x[(size_t)r * NN + col]       - acc[mi][nj][0] * cs0;
            const float d01 = x[(size_t)r * NN + col + 1]   - acc[mi][nj][1] * cs1;
            const float d10 = x[(size_t)(r + 8) * NN + col]     - acc[mi][nj][2] * cs0;
            const float d11 = x[(size_t)(r + 8) * NN + col + 1] - acc[mi][nj][3] * cs1;
            __nv_bfloat162 h2, l2;
            split_pack(d00, d01, h2, l2);
            *(__nv_bfloat162*)&g_dhi[base + (size_t)r * NN + col] = h2;
            *(__nv_bfloat162*)&g_dlo[base + (size_t)r * NN + col] = l2;
            split_pack(d10, d11, h2, l2);
            *(__nv_bfloat162*)&g_dhi[base + (size_t)(r + 8) * NN + col] = h2;
            *(__nv_bfloat162*)&g_dlo[base + (size_t)(r + 8) * NN + col] = l2;
        }
}

// ---------------- fused energy + exp + rowsum -> U bf16 ----------------
#define QA_ST 72
#define KB_ST 136

__global__ __launch_bounds__(256)
void attn_kernel()
{
    extern __shared__ __align__(16) char dsm[];
    __nv_bfloat16* sQ = (__nv_bfloat16*)dsm;
    __nv_bfloat16* sK = sQ + 2 * 128 * QA_ST;
    float* s_rs = (float*)(sK + 2 * 2 * 64 * KB_ST);

    const int cg = blockIdx.x;          // column group: 4 tiles of 128 = 512 cols
    const int b  = blockIdx.z;
    const int r0 = blockIdx.y * 128;
    const int tid = threadIdx.x;
    const int lane = tid & 31, warp = tid >> 5;
    const int wm = warp & 3, wn = warp >> 2;

    if (tid < 128) s_rs[tid] = 0.f;

    const uint32_t sQb = (uint32_t)__cvta_generic_to_shared(sQ);
    const uint32_t sKb = (uint32_t)__cvta_generic_to_shared(sK);

    const __nv_bfloat16* Qhi = g_Qthi + (size_t)b * NN * CQ;
    const __nv_bfloat16* Qlo = g_Qtlo + (size_t)b * NN * CQ;
#pragma unroll
    for (int p = 0; p < 4; p++) {
        const int idx = p * 256 + tid;
        const int row = idx >> 3, c8 = (idx & 7) * 8;
        cpasync16(sQb + (uint32_t)(row * QA_ST + c8) * 2,
                  Qhi + (size_t)(r0 + row) * CQ + c8);
        cpasync16(sQb + (uint32_t)(128 * QA_ST + row * QA_ST + c8) * 2,
                  Qlo + (size_t)(r0 + row) * CQ + c8);
    }
    cp_commit();

    const __nv_bfloat16* Khi = g_Khi + (size_t)b * CQ * NN;
    const __nv_bfloat16* Klo = g_Klo + (size_t)b * CQ * NN;
    const int kr = tid >> 4, kc8 = (tid & 15) * 8;

    auto issueK = [&](int tile, int stage) {
        const int c0 = (cg * 4 + tile) * 128;
        const uint32_t base = sKb + (uint32_t)stage * (2 * 64 * KB_ST * 2);
#pragma unroll
        for (int c = 0; c < 4; c++) {
            const int r = kr + c * 16;
            cpasync16(base + (uint32_t)(r * KB_ST + kc8) * 2,
                      Khi + (size_t)r * NN + c0 + kc8);
            cpasync16(base + (uint32_t)(64 * KB_ST + r * KB_ST + kc8) * 2,
                      Klo + (size_t)r * NN + c0 + kc8);
        }
        cp_commit();
    };

    issueK(0, 0);

    const int lr = lane & 15, lc8 = (lane >> 4) * 8;
    const uint32_t aBase = sQb + (uint32_t)((wm * 32 + lr) * QA_ST + lc8) * 2;
    const uint32_t bBase = sKb + (uint32_t)(lr * KB_ST + wn * 64 + lc8) * 2;
    constexpr uint32_t QPLANE = 128 * QA_ST * 2;
    constexpr uint32_t KPLANE = 64 * KB_ST * 2;
    constexpr uint32_t KSTAGE = 2 * KPLANE;

    const int gid = lane >> 2, t4 = lane & 3;
    float rowsum[2][2] = {{0.f, 0.f}, {0.f, 0.f}};
    __nv_bfloat16* U = g_A + (size_t)b * NN * NN;

    for (int tile = 0; tile < 4; tile++) {
        const int cur = tile & 1;
        if (tile + 1 < 4) {
            issueK(tile + 1, cur ^ 1);
            asm volatile("cp.async.wait_group 1;" ::: "memory");
        } else {
            asm volatile("cp.async.wait_group 0;" ::: "memory");
        }
        __syncthreads();

        const uint32_t bS = cur * KSTAGE;

        float acc[2][8][4];
#pragma unroll
        for (int i = 0; i < 2; i++)
#pragma unroll
            for (int j = 0; j < 8; j++)
#pragma unroll
                for (int k = 0; k < 4; k++) acc[i][j][k] = 0.f;

#pragma unroll
        for (int ch = 0; ch < 4; ch++) {
            uint32_t ah[2][4], al[2][4];
#pragma unroll
            for (int mi = 0; mi < 2; mi++) {
                ldsm4(ah[mi], aBase + ch * 32 + mi * 16 * QA_ST * 2);
                ldsm4(al[mi], aBase + QPLANE + ch * 32 + mi * 16 * QA_ST * 2);
            }
            uint32_t bh[4][4], bl[4][4];
#pragma unroll
            for (int j = 0; j < 4; j++) {
                ldsm4t(bh[j], bBase + bS + ch * 16 * KB_ST * 2 + j * 16 * 2);
                ldsm4t(bl[j], bBase + bS + KPLANE + ch * 16 * KB_ST * 2 + j * 16 * 2);
            }
#pragma unroll
            for (int mi = 0; mi < 2; mi++)
#pragma unroll
                for (int j = 0; j < 4; j++) {
                    mma16816(acc[mi][2 * j],     ah[mi], &bh[j][0]);
                    mma16816(acc[mi][2 * j + 1], ah[mi], &bh[j][2]);
                    mma16816(acc[mi][2 * j],     ah[mi], &bl[j][0]);
                    mma16816(acc[mi][2 * j + 1], ah[mi], &bl[j][2]);
                    mma16816(acc[mi][2 * j],     al[mi], &bh[j][0]);
                    mma16816(acc[mi][2 * j + 1], al[mi], &bh[j][2]);
                }
        }

        const int c0 = (cg * 4 + tile) * 128;
#pragma unroll
        for (int mi = 0; mi < 2; mi++)
#pragma unroll
            for (int nj = 0; nj < 8; nj++) {
                const int row = r0 + wm * 32 + mi * 16 + gid;
                const int col = c0 + wn * 64 + nj * 8 + t4 * 2;
                const float e00 = __expf(acc[mi][nj][0]);
                const float e01 = __expf(acc[mi][nj][1]);
                const float e10 = __expf(acc[mi][nj][2]);
                const float e11 = __expf(acc[mi][nj][3]);
                rowsum[mi][0] += e00 + e01;
                rowsum[mi][1] += e10 + e11;
                __nv_bfloat162 p0, p1;
                p0.x = __float2bfloat16(e00); p0.y = __float2bfloat16(e01);
                p1.x = __float2bfloat16(e10); p1.y = __float2bfloat16(e11);
                *(__nv_bfloat162*)&U[(size_t)row * NN + col] = p0;
                *(__nv_bfloat162*)&U[(size_t)(row + 8) * NN + col] = p1;
            }
        __syncthreads();
    }

#pragma unroll
    for (int mi = 0; mi < 2; mi++)
#pragma unroll
        for (int h = 0; h < 2; h++) {
            float v = rowsum[mi][h];
            v += __shfl_xor_sync(0xffffffffu, v, 1);
            v += __shfl_xor_sync(0xffffffffu, v, 2);
            if (t4 == 0) atomicAdd(&s_rs[wm * 32 + mi * 16 + gid + h * 8], v);
        }
    __syncthreads();
    if (tid < 128) g_rspart[(size_t)cg * BB * NN + b * NN + r0 + tid] = s_rs[tid];
}

// ---------------- invrs: reduce 8 rowsum partials ----------------
__global__ void invrs_kernel()
{
    const int i = blockIdx.x * 256 + threadIdx.x;   // over BB*NN
    float s = 0.f;
#pragma unroll
    for (int p = 0; p < 8; p++) s += g_rspart[(size_t)p * BB * NN + i];
    g_invrs[i] = 1.0f / s;
}

// ---------------- V' = V_fp32 * invrs[n] -> single bf16 plane ----------------
__global__ void vrescale_kernel()
{
    const int b = blockIdx.z;
    const size_t i4 = (size_t)blockIdx.x * 256 + threadIdx.x;   // over CC*NN/4
    const float4 v = ((const float4*)(g_V + (size_t)b * CC * NN))[i4];
    const int n4 = (int)((i4 * 4) & (NN - 1));
    const float4 w = *(const float4*)&g_invrs[b * NN + n4];
    __nv_bfloat162 p0, p1;
    p0.x = __float2bfloat16(v.x * w.x); p0.y = __float2bfloat16(v.y * w.y);
    p1.x = __float2bfloat16(v.z * w.z); p1.y = __float2bfloat16(v.w * w.w);
    uint2 o;
    o.x = *(uint32_t*)&p0; o.y = *(uint32_t*)&p1;
    ((uint2*)(g_Vhi + (size_t)b * CC * NN))[i4] = o;
}

// ---------------- weighted column sums ----------------
__global__ void colsum_kernel()
{
    const int m2 = blockIdx.x * 256 + threadIdx.x;
    const int b = blockIdx.z;
    const int n0 = blockIdx.y * 128;
    const __nv_bfloat162* A2 = (const __nv_bfloat162*)(g_A + (size_t)b * NN * NN);
    float s0 = 0.f, s1 = 0.f;
#pragma unroll 4
    for (int n = 0; n < 128; n++) {
        const float w = g_invrs[b * NN + n0 + n];
        const __nv_bfloat162 a = A2[(size_t)(n0 + n) * (NN / 2) + m2];
        s0 += __bfloat162float(a.x) * w;
        s1 += __bfloat162float(a.y) * w;
    }
    atomicAdd(&g_colsum[b * NN + 2 * m2 + 0], s0);
    atomicAdd(&g_colsum[b * NN + 2 * m2 + 1], s1);
}

// ---------------- splits ----------------
__global__ void split4_kernel(const float* __restrict__ src, size_t srcBS,
                              __nv_bfloat16* __restrict__ hi, __nv_bfloat16* __restrict__ lo,
                              size_t dstBS)
{
    const size_t i4 = (size_t)blockIdx.x * 256 + threadIdx.x;
    const float4 v = ((const float4*)(src + (size_t)blockIdx.z * srcBS))[i4];
    __nv_bfloat162 ha, la, hb, lb;
    split_pack(v.x, v.y, ha, la);
    split_pack(v.z, v.w, hb, lb);
    uint2 hv, lv;
    hv.x = *(uint32_t*)&ha; hv.y = *(uint32_t*)&hb;
    lv.x = *(uint32_t*)&la; lv.y = *(uint32_t*)&lb;
    ((uint2*)(hi + (size_t)blockIdx.z * dstBS))[i4] = hv;
    ((uint2*)(lo + (size_t)blockIdx.z * dstBS))[i4] = lv;
}

__global__ void wqkv_split_kernel(const float* __restrict__ Wq, const float* __restrict__ Wk,
                                  const float* __restrict__ Wv)
{
    const int t = blockIdx.x * 256 + threadIdx.x;
    float v;
    if (t < 64 * CC) v = Wq[t];
    else if (t < 128 * CC) v = Wk[t - 64 * CC];
    else v = Wv[t - 128 * CC];
    __nv_bfloat16 h, l;
    split1(v, h, l);
    g_Wqkvhi[t] = h; g_Wqkvlo[t] = l;
}

// ---------------- misc ----------------
__global__ void zero_kernel()
{
    const int t = blockIdx.x * 256 + threadIdx.x;
    if (t < CC) { g_sum[t] = 0.f; g_sumsq[t] = 0.f; }
    if (t < BB * NN) g_colsum[t] = 0.f;
}

__global__ void bn_finalize_kernel(const float* __restrict__ gamma, const float* __restrict__ beta)
{
    const int c = threadIdx.x;
    const float cnt = (float)(BB * NN);
    const float mean = g_sum[c] / cnt;
    const float var = g_sumsq[c] / cnt - mean * mean;
    const float sc = gamma[c] * rsqrtf(var + 1e-5f);
    g_scale[c] = sc;
    g_shift[c] = beta[c] - mean * sc;
}

__global__ void final_kernel(const float* __restrict__ x, float* __restrict__ out)
{
    const size_t idx = (size_t)blockIdx.x * 256 + threadIdx.x;
    const int c = (int)((idx >> 12) & (CC - 1));
    const float t = g_T[idx] * g_scale[c] + g_shift[c];
    out[idx] = x[idx] + fmaxf(t, 0.f);
}

// ---------------- launch ----------------
extern "C" void kernel_launch(void* const* d_in, const int* in_sizes, int n_in,
                              void* d_out, int out_size)
{
    const float* x     = (const float*)d_in[0];
    const float* Wq    = (const float*)d_in[1];
    const float* Wk    = (const float*)d_in[2];
    const float* Wv    = (const float*)d_in[3];
    const float* bv    = (const float*)d_in[4];
    const float* Wt    = (const float*)d_in[5];
    const float* bt    = (const float*)d_in[6];
    const float* gamma = (const float*)d_in[7];
    const float* beta  = (const float*)d_in[8];
    float* out = (float*)d_out;

    float *pT;
    __nv_bfloat16 *pA, *pXhi, *pXlo, *pVhi, *pDhi, *pDlo;
    __nv_bfloat16 *pWqkvhi, *pWqkvlo, *pWthi, *pWtlo;
    cudaGetSymbolAddress((void**)&pT, g_T);
    cudaGetSymbolAddress((void**)&pA, g_A);
    cudaGetSymbolAddress((void**)&pXhi, g_xhi);
    cudaGetSymbolAddress((void**)&pXlo, g_xlo);
    cudaGetSymbolAddress((void**)&pVhi, g_Vhi);
    cudaGetSymbolAddress((void**)&pDhi, g_dhi);
    cudaGetSymbolAddress((void**)&pDlo, g_dlo);
    cudaGetSymbolAddress((void**)&pWqkvhi, g_Wqkvhi);
    cudaGetSymbolAddress((void**)&pWqkvlo, g_Wqkvlo);
    cudaGetSymbolAddress((void**)&pWthi, g_Wthi);
    cudaGetSymbolAddress((void**)&pWtlo, g_Wtlo);

    const int attn_smem = (2 * 128 * QA_ST + 2 * 2 * 64 * KB_ST) * 2 + 128 * 4;
    cudaFuncSetAttribute(attn_kernel, cudaFuncAttributeMaxDynamicSharedMemorySize, attn_smem);

    const int smem_22 = 4 * (2 * 128 * SA_STRIDE * 2 + 2 * 16 * SB_STRIDE * 2);  // 83968
    const int smem_xr = 4 * (256 * XA_ST * 2 + 16 * XB_ST * 2);                   // 58368
    cudaFuncSetAttribute(mma_gemm_kernel<2, 2, 1>, cudaFuncAttributeMaxDynamicSharedMemorySize, smem_22);
    cudaFuncSetAttribute(mma_gemm_kernel<2, 2, 2>, cudaFuncAttributeMaxDynamicSharedMemorySize, smem_22);
    cudaFuncSetAttribute(xr_gemm_kernel, cudaFuncAttributeMaxDynamicSharedMemorySize, smem_xr);

    zero_kernel<<<BB * NN / 256, 256>>>();
    wqkv_split_kernel<<<384 * CC / 256, 256>>>(Wq, Wk, Wv);
    split4_kernel<<<dim3(CC * CC / 1024, 1, 1), 256>>>(Wt, 0, pWthi, pWtlo, 0);
    split4_kernel<<<dim3(CC * NN / 1024, 1, BB), 256>>>(x, (size_t)CC * NN, pXhi, pXlo, (size_t)CC * NN);

    // stacked QKV projection: [384,256] @ [256,4096]; epilogue writes Qt/K splits + V fp32
    mma_gemm_kernel<2, 2, 1><<<dim3(NN / 128, 3, BB), 256, smem_22>>>(
        pWqkvhi, pWqkvlo, CC, 0,
        pXhi, pXlo, (size_t)CC * NN,
        pT /*unused*/, 0, CC, bv);

    // fused energy + exp + rowsum -> U (bf16), rowsum partials (column-split grid)
    attn_kernel<<<dim3(8, NN / 128, BB), 256, attn_smem>>>();

    // invrs = 1 / sum of 8 partials
    invrs_kernel<<<BB * NN / 256, 256>>>();

    // V' = V_fp32 * invrs[n] -> single bf16 plane
    vrescale_kernel<<<dim3(CC * NN / 1024, 1, BB), 256>>>();

    // weighted column sums for L1 renorm
    colsum_kernel<<<dim3(NN / 512, NN / 128, BB), 256>>>();

    // x_r = V' @ U, retiled M=256 x N=64 (U read once); epilogue d = x - xr*cs -> splits
    xr_gemm_kernel<<<dim3(NN / 64, 1, BB), 256, smem_xr>>>(pVhi, pA, x);

    // t = Wt @ d + bt, with BN stats -> g_T
    mma_gemm_kernel<2, 2, 2><<<dim3(NN / 128, CC / 128, BB), 256, smem_22>>>(
        pWthi, pWtlo, CC, 0,
        pDhi, pDlo, (size_t)CC * NN,
        pT, (size_t)CC * NN, CC, bt);

    bn_finalize_kernel<<<1, CC>>>(gamma, beta);

    final_kernel<<<(size_t)BB * CC * NN / 256, 256>>>(x, out);
}

// round 12
// speedup vs baseline: 1.0365x; 1.0365x over previous
#include <cuda_runtime.h>
#include <cuda_bf16.h>
#include <cstdint>

#define BB 4
#define CC 256
#define CQ 64
#define NN 4096

// ---------------- scratch (device globals; no allocations) ----------------
__device__ __nv_bfloat16 g_A[(size_t)BB * NN * NN];     // U = exp(E), bf16, unnormalized
__device__ __nv_bfloat16 g_xhi[(size_t)BB * CC * NN];
__device__ __nv_bfloat16 g_xlo[(size_t)BB * CC * NN];
__device__ float g_V[(size_t)BB * CC * NN];             // V fp32 (pre-rescale)
__device__ __nv_bfloat16 g_Vhi[(size_t)BB * CC * NN];   // V' = V*invrs, single bf16 plane
__device__ __nv_bfloat16 g_dhi[(size_t)BB * CC * NN];   // d = x - xr*colscale, split
__device__ __nv_bfloat16 g_dlo[(size_t)BB * CC * NN];
__device__ __nv_bfloat16 g_Qthi[(size_t)BB * NN * CQ];  // Q transposed [n][o]
__device__ __nv_bfloat16 g_Qtlo[(size_t)BB * NN * CQ];
__device__ __nv_bfloat16 g_Khi[(size_t)BB * CQ * NN];
__device__ __nv_bfloat16 g_Klo[(size_t)BB * CQ * NN];
__device__ __nv_bfloat16 g_Wqkvhi[384 * CC];            // Wq(64) ; Wk(64) ; Wv(256) rows
__device__ __nv_bfloat16 g_Wqkvlo[384 * CC];
__device__ __nv_bfloat16 g_Wthi[CC * CC];
__device__ __nv_bfloat16 g_Wtlo[CC * CC];
__device__ float g_T[(size_t)BB * CC * NN];
__device__ float g_rspart[8 * BB * NN];                 // per-colgroup rowsum partials
__device__ float g_invrs[BB * NN];                      // 1 / softmax row sums
__device__ float g_colsum[BB * NN];
__device__ float g_sum[CC];
__device__ float g_sumsq[CC];
__device__ float g_scale[CC];
__device__ float g_shift[CC];

// ---------------- PTX helpers ----------------
__device__ __forceinline__ void mma16816(float* c, const uint32_t* a, const uint32_t* b) {
    asm volatile(
        "mma.sync.aligned.m16n8k16.row.col.f32.bf16.bf16.f32 "
        "{%0,%1,%2,%3}, {%4,%5,%6,%7}, {%8,%9}, {%0,%1,%2,%3};\n"
        : "+f"(c[0]), "+f"(c[1]), "+f"(c[2]), "+f"(c[3])
        : "r"(a[0]), "r"(a[1]), "r"(a[2]), "r"(a[3]), "r"(b[0]), "r"(b[1]));
}
__device__ __forceinline__ void ldsm4(uint32_t* r, uint32_t addr) {
    asm volatile("ldmatrix.sync.aligned.m8n8.x4.shared.b16 {%0,%1,%2,%3}, [%4];"
        : "=r"(r[0]), "=r"(r[1]), "=r"(r[2]), "=r"(r[3]) : "r"(addr));
}
__device__ __forceinline__ void ldsm4t(uint32_t* r, uint32_t addr) {
    asm volatile("ldmatrix.sync.aligned.m8n8.x4.trans.shared.b16 {%0,%1,%2,%3}, [%4];"
        : "=r"(r[0]), "=r"(r[1]), "=r"(r[2]), "=r"(r[3]) : "r"(addr));
}
__device__ __forceinline__ void cpasync16(uint32_t saddr, const void* g) {
    asm volatile("cp.async.cg.shared.global [%0], [%1], 16;" :: "r"(saddr), "l"(g));
}
__device__ __forceinline__ void cp_commit() { asm volatile("cp.async.commit_group;" ::: "memory"); }

__device__ __forceinline__ void split1(float v, __nv_bfloat16& h, __nv_bfloat16& l) {
    h = __float2bfloat16(v);
    l = __float2bfloat16(v - __bfloat162float(h));
}
__device__ __forceinline__ void split_pack(float a, float b, __nv_bfloat162& hi2, __nv_bfloat162& lo2) {
    __nv_bfloat16 ha, la, hb, lb;
    split1(a, ha, la); split1(b, hb, lb);
    hi2.x = ha; hi2.y = hb;
    lo2.x = la; lo2.y = lb;
}

// ---------------- unified bf16-split tensor-core GEMM, 4-stage pipeline ----------------
// (QKV projection and transform)
#define SA_STRIDE 24
#define SB_STRIDE 136

template<int NA, int NB, int EPI>
__global__ __launch_bounds__(256)
void mma_gemm_kernel(const __nv_bfloat16* __restrict__ Ahi, const __nv_bfloat16* __restrict__ Alo,
                     int lda, size_t aBS,
                     const __nv_bfloat16* __restrict__ B0, const __nv_bfloat16* __restrict__ B1,
                     size_t bBS,
                     float* __restrict__ C, size_t cBS, int K,
                     const float* __restrict__ bias)
{
    extern __shared__ __align__(16) char dynsm[];
    constexpr uint32_t A_PLANE = 128 * SA_STRIDE * 2;          // 6144
    constexpr uint32_t B_PLANE = 16 * SB_STRIDE * 2;           // 4352
    constexpr uint32_t STAGE   = NA * A_PLANE + NB * B_PLANE;

    const int bz = blockIdx.z;
    Ahi += (size_t)bz * aBS;
    if (NA == 2) Alo += (size_t)bz * aBS;
    B0  += (size_t)bz * bBS;
    if (NB == 2) B1 += (size_t)bz * bBS;
    C += (size_t)bz * cBS;

    const int row0 = blockIdx.y * 128;
    const int col0 = blockIdx.x * 128;
    const int tid  = threadIdx.x;
    const int lane = tid & 31, warp = tid >> 5;
    const int wm = warp & 3;
    const int wn = warp >> 2;

    const int ar = tid >> 1, ac = (tid & 1) * 8;
    const int bk = tid >> 4, bc = (tid & 15) * 8;
    const size_t gA = (size_t)(row0 + ar) * lda + ac;
    const size_t gB = (size_t)bk * NN + col0 + bc;

    const uint32_t sbase = (uint32_t)__cvta_generic_to_shared(dynsm);
    const uint32_t sAst = (uint32_t)(ar * SA_STRIDE + ac) * 2;
    const uint32_t sBst = NA * A_PLANE + (uint32_t)(bk * SB_STRIDE + bc) * 2;

    float acc[2][8][4];
#pragma unroll
    for (int i = 0; i < 2; i++)
#pragma unroll
        for (int j = 0; j < 8; j++)
#pragma unroll
            for (int k = 0; k < 4; k++) acc[i][j][k] = 0.f;

    const int KT = K >> 4;

    auto issue = [&](int kt, int s) {
        const size_t ka = gA + (size_t)kt * 16;
        const size_t kb = gB + (size_t)kt * 16 * NN;
        const uint32_t st = sbase + (uint32_t)s * STAGE;
        cpasync16(st + sAst, Ahi + ka);
        if (NA == 2) cpasync16(st + A_PLANE + sAst, Alo + ka);
        cpasync16(st + sBst, B0 + kb);
        if (NB == 2) cpasync16(st + B_PLANE + sBst, B1 + kb);
    };

#pragma unroll
    for (int s = 0; s < 3; s++) { issue(s, s); cp_commit(); }

    const int lr = lane & 15, lc8 = (lane >> 4) * 8;
    const uint32_t aOff = ((wm * 32 + lr) * SA_STRIDE + lc8) * 2;
    const uint32_t bOff = NA * A_PLANE + (lr * SB_STRIDE + wn * 64 + lc8) * 2;

    for (int kt = 0; kt < KT; kt++) {
        asm volatile("cp.async.wait_group 2;" ::: "memory");
        __syncthreads();
        if (kt + 3 < KT) issue(kt + 3, (kt + 3) & 3);
        cp_commit();

        const uint32_t st = sbase + (uint32_t)(kt & 3) * STAGE;

        uint32_t ah[2][4], al[2][4];
#pragma unroll
        for (int mi = 0; mi < 2; mi++) {
            ldsm4(ah[mi], st + aOff + mi * 16 * SA_STRIDE * 2);
            if (NA == 2) ldsm4(al[mi], st + A_PLANE + aOff + mi * 16 * SA_STRIDE * 2);
        }
        uint32_t bh[4][4], bl[4][4];
#pragma unroll
        for (int j = 0; j < 4; j++) {
            ldsm4t(bh[j], st + bOff + j * 16 * 2);
            if (NB == 2) ldsm4t(bl[j], st + bOff + B_PLANE + j * 16 * 2);
        }
#pragma unroll
        for (int mi = 0; mi < 2; mi++) {
#pragma unroll
            for (int j = 0; j < 4; j++) {
                mma16816(acc[mi][2 * j],     ah[mi], &bh[j][0]);
                mma16816(acc[mi][2 * j + 1], ah[mi], &bh[j][2]);
                if (NB == 2) {
                    mma16816(acc[mi][2 * j],     ah[mi], &bl[j][0]);
                    mma16816(acc[mi][2 * j + 1], ah[mi], &bl[j][2]);
                }
                if (NA == 2) {
                    mma16816(acc[mi][2 * j],     al[mi], &bh[j][0]);
                    mma16816(acc[mi][2 * j + 1], al[mi], &bh[j][2]);
                }
            }
        }
    }

    const int gid = lane >> 2, t4 = lane & 3;

    if (EPI == 1) {
        const int by = blockIdx.y;
#pragma unroll
        for (int mi = 0; mi < 2; mi++)
#pragma unroll
            for (int nj = 0; nj < 8; nj++) {
                const int r = row0 + wm * 32 + mi * 16 + gid;
                const int col = col0 + wn * 64 + nj * 8 + t4 * 2;
                const float v00 = acc[mi][nj][0], v01 = acc[mi][nj][1];
                const float v10 = acc[mi][nj][2], v11 = acc[mi][nj][3];
                if (by == 0) {
                    if (r < 64) {  // Q -> transposed split [n][o]
                        const size_t base = (size_t)bz * NN * CQ;
                        __nv_bfloat16 h, l;
                        split1(v00, h, l); g_Qthi[base + (size_t)col * CQ + r] = h;       g_Qtlo[base + (size_t)col * CQ + r] = l;
                        split1(v01, h, l); g_Qthi[base + (size_t)(col + 1) * CQ + r] = h; g_Qtlo[base + (size_t)(col + 1) * CQ + r] = l;
                        split1(v10, h, l); g_Qthi[base + (size_t)col * CQ + r + 8] = h;       g_Qtlo[base + (size_t)col * CQ + r + 8] = l;
                        split1(v11, h, l); g_Qthi[base + (size_t)(col + 1) * CQ + r + 8] = h; g_Qtlo[base + (size_t)(col + 1) * CQ + r + 8] = l;
                    } else {       // K -> split [o][n]
                        const int kr = r - 64;
                        const size_t base = (size_t)bz * CQ * NN;
                        __nv_bfloat162 h2, l2;
                        split_pack(v00, v01, h2, l2);
                        *(__nv_bfloat162*)&g_Khi[base + (size_t)kr * NN + col] = h2;
                        *(__nv_bfloat162*)&g_Klo[base + (size_t)kr * NN + col] = l2;
                        split_pack(v10, v11, h2, l2);
                        *(__nv_bfloat162*)&g_Khi[base + (size_t)(kr + 8) * NN + col] = h2;
                        *(__nv_bfloat162*)&g_Klo[base + (size_t)(kr + 8) * NN + col] = l2;
                    }
                } else {           // V rows (+bias) -> fp32 (single rounding happens in vrescale)
                    const int vr = r - 128;
                    float* dst = g_V + (size_t)bz * CC * NN;
                    const float b0 = bias[vr], b1 = bias[vr + 8];
                    *(float2*)&dst[(size_t)vr * NN + col]       = make_float2(v00 + b0, v01 + b0);
                    *(float2*)&dst[(size_t)(vr + 8) * NN + col] = make_float2(v10 + b1, v11 + b1);
                }
            }
    }

    if (EPI == 2) {
        float ssum[2][2] = {{0.f, 0.f}, {0.f, 0.f}};
        float ssq[2][2]  = {{0.f, 0.f}, {0.f, 0.f}};
#pragma unroll
        for (int mi = 0; mi < 2; mi++)
#pragma unroll
            for (int nj = 0; nj < 8; nj++) {
                const int r = row0 + wm * 32 + mi * 16 + gid;
                const int col = col0 + wn * 64 + nj * 8 + t4 * 2;
                const float b0 = bias[r], b1 = bias[r + 8];
                const float v00 = acc[mi][nj][0] + b0, v01 = acc[mi][nj][1] + b0;
                const float v10 = acc[mi][nj][2] + b1, v11 = acc[mi][nj][3] + b1;
                *(float2*)&C[(size_t)r * NN + col]       = make_float2(v00, v01);
                *(float2*)&C[(size_t)(r + 8) * NN + col] = make_float2(v10, v11);
                ssum[mi][0] += v00 + v01;  ssq[mi][0] += v00 * v00 + v01 * v01;
                ssum[mi][1] += v10 + v11;  ssq[mi][1] += v10 * v10 + v11 * v11;
            }
#pragma unroll
        for (int mi = 0; mi < 2; mi++)
#pragma unroll
            for (int h = 0; h < 2; h++) {
                const int r = row0 + wm * 32 + mi * 16 + gid + h * 8;
                atomicAdd(&g_sum[r], ssum[mi][h]);
                atomicAdd(&g_sumsq[r], ssq[mi][h]);
            }
    }
}

// ---------------- x_r GEMM: 128x128 tile, k-tile 32, 4-stage pipeline ----------------
// xr[c,m] = sum_n V'(c,n) * U(n,m); epilogue d = x - xr*colscale -> splits
#define XA_ST 40   // halves per A row (32 + 8 pad; 80B = 16*5, odd multiple -> conflict-free)
#define XB_ST 136  // halves per B row

__global__ __launch_bounds__(256)
void xr_gemm_kernel(const __nv_bfloat16* __restrict__ Vp, const __nv_bfloat16* __restrict__ U,
                    const float* __restrict__ x)
{
    extern __shared__ __align__(16) char dynsm[];
    constexpr uint32_t A_PLANE = 128 * XA_ST * 2;   // 10240
    constexpr uint32_t B_PLANE = 32 * XB_ST * 2;    // 8704
    constexpr uint32_t STAGE   = A_PLANE + B_PLANE; // 18944

    const int bz = blockIdx.z;
    Vp += (size_t)bz * CC * NN;
    U  += (size_t)bz * NN * NN;
    x  += (size_t)bz * CC * NN;

    const int row0 = blockIdx.y * 128;
    const int col0 = blockIdx.x * 128;
    const int tid  = threadIdx.x;
    const int lane = tid & 31, warp = tid >> 5;
    const int wm = warp & 3, wn = warp >> 2;

    // A: 128 rows x 32 halves = 512 vec16; 2 per thread
    const int av0 = tid * 2;
    const int ar0 = av0 >> 2,       ac0 = (av0 & 3) * 8;
    const int ar1 = (av0 + 1) >> 2, ac1 = ((av0 + 1) & 3) * 8;
    // B: 32 rows x 128 halves = 512 vec16; 2 per thread
    const int br0 = av0 >> 4,       bc0 = (av0 & 15) * 8;
    const int br1 = (av0 + 1) >> 4, bc1 = ((av0 + 1) & 15) * 8;

    const uint32_t sbase = (uint32_t)__cvta_generic_to_shared(dynsm);
    const uint32_t sA0 = (uint32_t)(ar0 * XA_ST + ac0) * 2;
    const uint32_t sA1 = (uint32_t)(ar1 * XA_ST + ac1) * 2;
    const uint32_t sB0 = A_PLANE + (uint32_t)(br0 * XB_ST + bc0) * 2;
    const uint32_t sB1 = A_PLANE + (uint32_t)(br1 * XB_ST + bc1) * 2;

    float acc[2][8][4];
#pragma unroll
    for (int i = 0; i < 2; i++)
#pragma unroll
        for (int j = 0; j < 8; j++)
#pragma unroll
            for (int k = 0; k < 4; k++) acc[i][j][k] = 0.f;

    auto issue = [&](int kt, int s) {
        const uint32_t st = sbase + (uint32_t)s * STAGE;
        const size_t k0 = (size_t)kt * 32;
        cpasync16(st + sA0, Vp + (size_t)(row0 + ar0) * NN + k0 + ac0);
        cpasync16(st + sA1, Vp + (size_t)(row0 + ar1) * NN + k0 + ac1);
        cpasync16(st + sB0, U + (k0 + br0) * NN + col0 + bc0);
        cpasync16(st + sB1, U + (k0 + br1) * NN + col0 + bc1);
    };

#pragma unroll
    for (int s = 0; s < 3; s++) { issue(s, s); cp_commit(); }

    const int lr = lane & 15, lc8 = (lane >> 4) * 8;
    const uint32_t aOff = ((wm * 32 + lr) * XA_ST + lc8) * 2;
    const uint32_t bOff = A_PLANE + (lr * XB_ST + wn * 64 + lc8) * 2;

    for (int kt = 0; kt < 128; kt++) {
        asm volatile("cp.async.wait_group 2;" ::: "memory");
        __syncthreads();
        if (kt + 3 < 128) issue(kt + 3, (kt + 3) & 3);
        cp_commit();

        const uint32_t st = sbase + (uint32_t)(kt & 3) * STAGE;

#pragma unroll
        for (int ch = 0; ch < 2; ch++) {
            uint32_t ah[2][4];
#pragma unroll
            for (int mi = 0; mi < 2; mi++)
                ldsm4(ah[mi], st + aOff + ch * 32 + mi * 16 * XA_ST * 2);
            uint32_t bh[4][4];
#pragma unroll
            for (int j = 0; j < 4; j++)
                ldsm4t(bh[j], st + bOff + ch * 16 * XB_ST * 2 + j * 16 * 2);
#pragma unroll
            for (int mi = 0; mi < 2; mi++)
#pragma unroll
                for (int j = 0; j < 4; j++) {
                    mma16816(acc[mi][2 * j],     ah[mi], &bh[j][0]);
                    mma16816(acc[mi][2 * j + 1], ah[mi], &bh[j][2]);
                }
        }
    }

    const int gid = lane >> 2, t4 = lane & 3;
#pragma unroll
    for (int mi = 0; mi < 2; mi++)
#pragma unroll
        for (int nj = 0; nj < 8; nj++) {
            const int r = row0 + wm * 32 + mi * 16 + gid;
            const int col = col0 + wn * 64 + nj * 8 + t4 * 2;
            const float cs0 = 1.0f / (1e-9f + g_colsum[bz * NN + col]);
            const float cs1 = 1.0f / (1e-9f + g_colsum[bz * NN + col + 1]);
            const size_t base = (size_t)bz * CC * NN;
            const float d00 = x[(size_t)r * NN + col]       - acc[mi][nj][0] * cs0;
            const float d01 = x[(size_t)r * NN + col + 1]   - acc[mi][nj][1] * cs1;
            const float d10 = x[(size_t)(r + 8) * NN + col]     - acc[mi][nj][2] * cs0;
            const float d11 = x[(size_t)(r + 8) * NN + col + 1] - acc[mi][nj][3] * cs1;
            __nv_bfloat162 h2, l2;
            split_pack(d00, d01, h2, l2);
            *(__nv_bfloat162*)&g_dhi[base + (size_t)r * NN + col] = h2;
            *(__nv_bfloat162*)&g_dlo[base + (size_t)r * NN + col] = l2;
            split_pack(d10, d11, h2, l2);
            *(__nv_bfloat162*)&g_dhi[base + (size_t)(r + 8) * NN + col] = h2;
            *(__nv_bfloat162*)&g_dlo[base + (size_t)(r + 8) * NN + col] = l2;
        }
}

// ---------------- fused energy + exp + rowsum -> U bf16 ----------------
#define QA_ST 72
#define KB_ST 136

__global__ __launch_bounds__(256)
void attn_kernel()
{
    extern __shared__ __align__(16) char dsm[];
    __nv_bfloat16* sQ = (__nv_bfloat16*)dsm;
    __nv_bfloat16* sK = sQ + 2 * 128 * QA_ST;
    float* s_rs = (float*)(sK + 2 * 2 * 64 * KB_ST);

    const int cg = blockIdx.x;          // column group: 4 tiles of 128 = 512 cols
    const int b  = blockIdx.z;
    const int r0 = blockIdx.y * 128;
    const int tid = threadIdx.x;
    const int lane = tid & 31, warp = tid >> 5;
    const int wm = warp & 3, wn = warp >> 2;

    if (tid < 128) s_rs[tid] = 0.f;

    const uint32_t sQb = (uint32_t)__cvta_generic_to_shared(sQ);
    const uint32_t sKb = (uint32_t)__cvta_generic_to_shared(sK);

    const __nv_bfloat16* Qhi = g_Qthi + (size_t)b * NN * CQ;
    const __nv_bfloat16* Qlo = g_Qtlo + (size_t)b * NN * CQ;
#pragma unroll
    for (int p = 0; p < 4; p++) {
        const int idx = p * 256 + tid;
        const int row = idx >> 3, c8 = (idx & 7) * 8;
        cpasync16(sQb + (uint32_t)(row * QA_ST + c8) * 2,
                  Qhi + (size_t)(r0 + row) * CQ + c8);
        cpasync16(sQb + (uint32_t)(128 * QA_ST + row * QA_ST + c8) * 2,
                  Qlo + (size_t)(r0 + row) * CQ + c8);
    }
    cp_commit();

    const __nv_bfloat16* Khi = g_Khi + (size_t)b * CQ * NN;
    const __nv_bfloat16* Klo = g_Klo + (size_t)b * CQ * NN;
    const int kr = tid >> 4, kc8 = (tid & 15) * 8;

    auto issueK = [&](int tile, int stage) {
        const int c0 = (cg * 4 + tile) * 128;
        const uint32_t base = sKb + (uint32_t)stage * (2 * 64 * KB_ST * 2);
#pragma unroll
        for (int c = 0; c < 4; c++) {
            const int r = kr + c * 16;
            cpasync16(base + (uint32_t)(r * KB_ST + kc8) * 2,
                      Khi + (size_t)r * NN + c0 + kc8);
            cpasync16(base + (uint32_t)(64 * KB_ST + r * KB_ST + kc8) * 2,
                      Klo + (size_t)r * NN + c0 + kc8);
        }
        cp_commit();
    };

    issueK(0, 0);

    const int lr = lane & 15, lc8 = (lane >> 4) * 8;
    const uint32_t aBase = sQb + (uint32_t)((wm * 32 + lr) * QA_ST + lc8) * 2;
    const uint32_t bBase = sKb + (uint32_t)(lr * KB_ST + wn * 64 + lc8) * 2;
    constexpr uint32_t QPLANE = 128 * QA_ST * 2;
    constexpr uint32_t KPLANE = 64 * KB_ST * 2;
    constexpr uint32_t KSTAGE = 2 * KPLANE;

    const int gid = lane >> 2, t4 = lane & 3;
    float rowsum[2][2] = {{0.f, 0.f}, {0.f, 0.f}};
    __nv_bfloat16* U = g_A + (size_t)b * NN * NN;

    for (int tile = 0; tile < 4; tile++) {
        const int cur = tile & 1;
        if (tile + 1 < 4) {
            issueK(tile + 1, cur ^ 1);
            asm volatile("cp.async.wait_group 1;" ::: "memory");
        } else {
            asm volatile("cp.async.wait_group 0;" ::: "memory");
        }
        __syncthreads();

        const uint32_t bS = cur * KSTAGE;

        float acc[2][8][4];
#pragma unroll
        for (int i = 0; i < 2; i++)
#pragma unroll
            for (int j = 0; j < 8; j++)
#pragma unroll
                for (int k = 0; k < 4; k++) acc[i][j][k] = 0.f;

#pragma unroll
        for (int ch = 0; ch < 4; ch++) {
            uint32_t ah[2][4], al[2][4];
#pragma unroll
            for (int mi = 0; mi < 2; mi++) {
                ldsm4(ah[mi], aBase + ch * 32 + mi * 16 * QA_ST * 2);
                ldsm4(al[mi], aBase + QPLANE + ch * 32 + mi * 16 * QA_ST * 2);
            }
            uint32_t bh[4][4], bl[4][4];
#pragma unroll
            for (int j = 0; j < 4; j++) {
                ldsm4t(bh[j], bBase + bS + ch * 16 * KB_ST * 2 + j * 16 * 2);
                ldsm4t(bl[j], bBase + bS + KPLANE + ch * 16 * KB_ST * 2 + j * 16 * 2);
            }
#pragma unroll
            for (int mi = 0; mi < 2; mi++)
#pragma unroll
                for (int j = 0; j < 4; j++) {
                    mma16816(acc[mi][2 * j],     ah[mi], &bh[j][0]);
                    mma16816(acc[mi][2 * j + 1], ah[mi], &bh[j][2]);
                    mma16816(acc[mi][2 * j],     ah[mi], &bl[j][0]);
                    mma16816(acc[mi][2 * j + 1], ah[mi], &bl[j][2]);
                    mma16816(acc[mi][2 * j],     al[mi], &bh[j][0]);
                    mma16816(acc[mi][2 * j + 1], al[mi], &bh[j][2]);
                }
        }

        const int c0 = (cg * 4 + tile) * 128;
#pragma unroll
        for (int mi = 0; mi < 2; mi++)
#pragma unroll
            for (int nj = 0; nj < 8; nj++) {
                const int row = r0 + wm * 32 + mi * 16 + gid;
                const int col = c0 + wn * 64 + nj * 8 + t4 * 2;
                const float e00 = __expf(acc[mi][nj][0]);
                const float e01 = __expf(acc[mi][nj][1]);
                const float e10 = __expf(acc[mi][nj][2]);
                const float e11 = __expf(acc[mi][nj][3]);
                rowsum[mi][0] += e00 + e01;
                rowsum[mi][1] += e10 + e11;
                __nv_bfloat162 p0, p1;
                p0.x = __float2bfloat16(e00); p0.y = __float2bfloat16(e01);
                p1.x = __float2bfloat16(e10); p1.y = __float2bfloat16(e11);
                *(__nv_bfloat162*)&U[(size_t)row * NN + col] = p0;
                *(__nv_bfloat162*)&U[(size_t)(row + 8) * NN + col] = p1;
            }
        __syncthreads();
    }

#pragma unroll
    for (int mi = 0; mi < 2; mi++)
#pragma unroll
        for (int h = 0; h < 2; h++) {
            float v = rowsum[mi][h];
            v += __shfl_xor_sync(0xffffffffu, v, 1);
            v += __shfl_xor_sync(0xffffffffu, v, 2);
            if (t4 == 0) atomicAdd(&s_rs[wm * 32 + mi * 16 + gid + h * 8], v);
        }
    __syncthreads();
    if (tid < 128) g_rspart[(size_t)cg * BB * NN + b * NN + r0 + tid] = s_rs[tid];
}

// ---------------- invrs: reduce 8 rowsum partials ----------------
__global__ void invrs_kernel()
{
    const int i = blockIdx.x * 256 + threadIdx.x;   // over BB*NN
    float s = 0.f;
#pragma unroll
    for (int p = 0; p < 8; p++) s += g_rspart[(size_t)p * BB * NN + i];
    g_invrs[i] = 1.0f / s;
}

// ---------------- V' = V_fp32 * invrs[n] -> single bf16 plane ----------------
__global__ void vrescale_kernel()
{
    const int b = blockIdx.z;
    const size_t i4 = (size_t)blockIdx.x * 256 + threadIdx.x;   // over CC*NN/4
    const float4 v = ((const float4*)(g_V + (size_t)b * CC * NN))[i4];
    const int n4 = (int)((i4 * 4) & (NN - 1));
    const float4 w = *(const float4*)&g_invrs[b * NN + n4];
    __nv_bfloat162 p0, p1;
    p0.x = __float2bfloat16(v.x * w.x); p0.y = __float2bfloat16(v.y * w.y);
    p1.x = __float2bfloat16(v.z * w.z); p1.y = __float2bfloat16(v.w * w.w);
    uint2 o;
    o.x = *(uint32_t*)&p0; o.y = *(uint32_t*)&p1;
    ((uint2*)(g_Vhi + (size_t)b * CC * NN))[i4] = o;
}

// ---------------- weighted column sums ----------------
__global__ void colsum_kernel()
{
    const int m2 = blockIdx.x * 256 + threadIdx.x;
    const int b = blockIdx.z;
    const int n0 = blockIdx.y * 128;
    const __nv_bfloat162* A2 = (const __nv_bfloat162*)(g_A + (size_t)b * NN * NN);
    float s0 = 0.f, s1 = 0.f;
#pragma unroll 4
    for (int n = 0; n < 128; n++) {
        const float w = g_invrs[b * NN + n0 + n];
        const __nv_bfloat162 a = A2[(size_t)(n0 + n) * (NN / 2) + m2];
        s0 += __bfloat162float(a.x) * w;
        s1 += __bfloat162float(a.y) * w;
    }
    atomicAdd(&g_colsum[b * NN + 2 * m2 + 0], s0);
    atomicAdd(&g_colsum[b * NN + 2 * m2 + 1], s1);
}

// ---------------- splits ----------------
__global__ void split4_kernel(const float* __restrict__ src, size_t srcBS,
                              __nv_bfloat16* __restrict__ hi, __nv_bfloat16* __restrict__ lo,
                              size_t dstBS)
{
    const size_t i4 = (size_t)blockIdx.x * 256 + threadIdx.x;
    const float4 v = ((const float4*)(src + (size_t)blockIdx.z * srcBS))[i4];
    __nv_bfloat162 ha, la, hb, lb;
    split_pack(v.x, v.y, ha, la);
    split_pack(v.z, v.w, hb, lb);
    uint2 hv, lv;
    hv.x = *(uint32_t*)&ha; hv.y = *(uint32_t*)&hb;
    lv.x = *(uint32_t*)&la; lv.y = *(uint32_t*)&lb;
    ((uint2*)(hi + (size_t)blockIdx.z * dstBS))[i4] = hv;
    ((uint2*)(lo + (size_t)blockIdx.z * dstBS))[i4] = lv;
}

__global__ void wqkv_split_kernel(const float* __restrict__ Wq, const float* __restrict__ Wk,
                                  const float* __restrict__ Wv)
{
    const int t = blockIdx.x * 256 + threadIdx.x;
    float v;
    if (t < 64 * CC) v = Wq[t];
    else if (t < 128 * CC) v = Wk[t - 64 * CC];
    else v = Wv[t - 128 * CC];
    __nv_bfloat16 h, l;
    split1(v, h, l);
    g_Wqkvhi[t] = h; g_Wqkvlo[t] = l;
}

// ---------------- misc ----------------
__global__ void zero_kernel()
{
    const int t = blockIdx.x * 256 + threadIdx.x;
    if (t < CC) { g_sum[t] = 0.f; g_sumsq[t] = 0.f; }
    if (t < BB * NN) g_colsum[t] = 0.f;
}

__global__ void bn_finalize_kernel(const float* __restrict__ gamma, const float* __restrict__ beta)
{
    const int c = threadIdx.x;
    const float cnt = (float)(BB * NN);
    const float mean = g_sum[c] / cnt;
    const float var = g_sumsq[c] / cnt - mean * mean;
    const float sc = gamma[c] * rsqrtf(var + 1e-5f);
    g_scale[c] = sc;
    g_shift[c] = beta[c] - mean * sc;
}

__global__ void final_kernel(const float* __restrict__ x, float* __restrict__ out)
{
    const size_t idx = (size_t)blockIdx.x * 256 + threadIdx.x;
    const int c = (int)((idx >> 12) & (CC - 1));
    const float t = g_T[idx] * g_scale[c] + g_shift[c];
    out[idx] = x[idx] + fmaxf(t, 0.f);
}

// ---------------- launch ----------------
extern "C" void kernel_launch(void* const* d_in, const int* in_sizes, int n_in,
                              void* d_out, int out_size)
{
    const float* x     = (const float*)d_in[0];
    const float* Wq    = (const float*)d_in[1];
    const float* Wk    = (const float*)d_in[2];
    const float* Wv    = (const float*)d_in[3];
    const float* bv    = (const float*)d_in[4];
    const float* Wt    = (const float*)d_in[5];
    const float* bt    = (const float*)d_in[6];
    const float* gamma = (const float*)d_in[7];
    const float* beta  = (const float*)d_in[8];
    float* out = (float*)d_out;

    float *pT;
    __nv_bfloat16 *pA, *pXhi, *pXlo, *pVhi, *pDhi, *pDlo;
    __nv_bfloat16 *pWqkvhi, *pWqkvlo, *pWthi, *pWtlo;
    cudaGetSymbolAddress((void**)&pT, g_T);
    cudaGetSymbolAddress((void**)&pA, g_A);
    cudaGetSymbolAddress((void**)&pXhi, g_xhi);
    cudaGetSymbolAddress((void**)&pXlo, g_xlo);
    cudaGetSymbolAddress((void**)&pVhi, g_Vhi);
    cudaGetSymbolAddress((void**)&pDhi, g_dhi);
    cudaGetSymbolAddress((void**)&pDlo, g_dlo);
    cudaGetSymbolAddress((void**)&pWqkvhi, g_Wqkvhi);
    cudaGetSymbolAddress((void**)&pWqkvlo, g_Wqkvlo);
    cudaGetSymbolAddress((void**)&pWthi, g_Wthi);
    cudaGetSymbolAddress((void**)&pWtlo, g_Wtlo);

    const int attn_smem = (2 * 128 * QA_ST + 2 * 2 * 64 * KB_ST) * 2 + 128 * 4;
    cudaFuncSetAttribute(attn_kernel, cudaFuncAttributeMaxDynamicSharedMemorySize, attn_smem);

    const int smem_22 = 4 * (2 * 128 * SA_STRIDE * 2 + 2 * 16 * SB_STRIDE * 2);  // 83968
    const int smem_xr = 4 * (128 * XA_ST * 2 + 32 * XB_ST * 2);                   // 75776
    cudaFuncSetAttribute(mma_gemm_kernel<2, 2, 1>, cudaFuncAttributeMaxDynamicSharedMemorySize, smem_22);
    cudaFuncSetAttribute(mma_gemm_kernel<2, 2, 2>, cudaFuncAttributeMaxDynamicSharedMemorySize, smem_22);
    cudaFuncSetAttribute(xr_gemm_kernel, cudaFuncAttributeMaxDynamicSharedMemorySize, smem_xr);

    zero_kernel<<<BB * NN / 256, 256>>>();
    wqkv_split_kernel<<<384 * CC / 256, 256>>>(Wq, Wk, Wv);
    split4_kernel<<<dim3(CC * CC / 1024, 1, 1), 256>>>(Wt, 0, pWthi, pWtlo, 0);
    split4_kernel<<<dim3(CC * NN / 1024, 1, BB), 256>>>(x, (size_t)CC * NN, pXhi, pXlo, (size_t)CC * NN);

    // stacked QKV projection: [384,256] @ [256,4096]; epilogue writes Qt/K splits + V fp32
    mma_gemm_kernel<2, 2, 1><<<dim3(NN / 128, 3, BB), 256, smem_22>>>(
        pWqkvhi, pWqkvlo, CC, 0,
        pXhi, pXlo, (size_t)CC * NN,
        pT /*unused*/, 0, CC, bv);

    // fused energy + exp + rowsum -> U (bf16), rowsum partials (column-split grid)
    attn_kernel<<<dim3(8, NN / 128, BB), 256, attn_smem>>>();

    // invrs = 1 / sum of 8 partials
    invrs_kernel<<<BB * NN / 256, 256>>>();

    // V' = V_fp32 * invrs[n] -> single bf16 plane
    vrescale_kernel<<<dim3(CC * NN / 1024, 1, BB), 256>>>();

    // weighted column sums for L1 renorm
    colsum_kernel<<<dim3(NN / 512, NN / 128, BB), 256>>>();

    // x_r = V' @ U, 128x128 tile, k-tile 32; epilogue d = x - xr*cs -> splits
    xr_gemm_kernel<<<dim3(NN / 128, CC / 128, BB), 256, smem_xr>>>(pVhi, pA, x);

    // t = Wt @ d + bt, with BN stats -> g_T
    mma_gemm_kernel<2, 2, 2><<<dim3(NN / 128, CC / 128, BB), 256, smem_22>>>(
        pWthi, pWtlo, CC, 0,
        pDhi, pDlo, (size_t)CC * NN,
        pT, (size_t)CC * NN, CC, bt);

    bn_finalize_kernel<<<1, CC>>>(gamma, beta);

    final_kernel<<<(size_t)BB * CC * NN / 256, 256>>>(x, out);
}

// round 13
// speedup vs baseline: 1.0536x; 1.0165x over previous
#include <cuda_runtime.h>
#include <cuda_bf16.h>
#include <cstdint>

#define BB 4
#define CC 256
#define CQ 64
#define NN 4096

// ---------------- scratch (device globals; no allocations) ----------------
__device__ __nv_bfloat16 g_A[(size_t)BB * NN * NN];     // U = exp(E), bf16, unnormalized
__device__ __nv_bfloat16 g_xhi[(size_t)BB * CC * NN];
__device__ __nv_bfloat16 g_xlo[(size_t)BB * CC * NN];
__device__ float g_V[(size_t)BB * CC * NN];             // V fp32 (pre-rescale)
__device__ __nv_bfloat16 g_Vhi[(size_t)BB * CC * NN];   // V' = V*invrs, single bf16 plane
__device__ __nv_bfloat16 g_dhi[(size_t)BB * CC * NN];   // d = x - xr*colscale, split
__device__ __nv_bfloat16 g_dlo[(size_t)BB * CC * NN];
__device__ __nv_bfloat16 g_Qthi[(size_t)BB * NN * CQ];  // Q transposed [n][o]
__device__ __nv_bfloat16 g_Qtlo[(size_t)BB * NN * CQ];
__device__ __nv_bfloat16 g_Khi[(size_t)BB * CQ * NN];
__device__ __nv_bfloat16 g_Klo[(size_t)BB * CQ * NN];
__device__ __nv_bfloat16 g_Wqkvhi[384 * CC];            // Wq(64) ; Wk(64) ; Wv(256) rows
__device__ __nv_bfloat16 g_Wqkvlo[384 * CC];
__device__ __nv_bfloat16 g_Wthi[CC * CC];
__device__ __nv_bfloat16 g_Wtlo[CC * CC];
__device__ float g_T[(size_t)BB * CC * NN];
__device__ float g_rspart[8 * BB * NN];                 // per-colgroup rowsum partials
__device__ float g_invrs[BB * NN];                      // 1 / softmax row sums
__device__ float g_colsum[BB * NN];
__device__ float g_sum[CC];
__device__ float g_sumsq[CC];

// ---------------- PTX helpers ----------------
__device__ __forceinline__ void mma16816(float* c, const uint32_t* a, const uint32_t* b) {
    asm volatile(
        "mma.sync.aligned.m16n8k16.row.col.f32.bf16.bf16.f32 "
        "{%0,%1,%2,%3}, {%4,%5,%6,%7}, {%8,%9}, {%0,%1,%2,%3};\n"
        : "+f"(c[0]), "+f"(c[1]), "+f"(c[2]), "+f"(c[3])
        : "r"(a[0]), "r"(a[1]), "r"(a[2]), "r"(a[3]), "r"(b[0]), "r"(b[1]));
}
__device__ __forceinline__ void ldsm4(uint32_t* r, uint32_t addr) {
    asm volatile("ldmatrix.sync.aligned.m8n8.x4.shared.b16 {%0,%1,%2,%3}, [%4];"
        : "=r"(r[0]), "=r"(r[1]), "=r"(r[2]), "=r"(r[3]) : "r"(addr));
}
__device__ __forceinline__ void ldsm4t(uint32_t* r, uint32_t addr) {
    asm volatile("ldmatrix.sync.aligned.m8n8.x4.trans.shared.b16 {%0,%1,%2,%3}, [%4];"
        : "=r"(r[0]), "=r"(r[1]), "=r"(r[2]), "=r"(r[3]) : "r"(addr));
}
__device__ __forceinline__ void cpasync16(uint32_t saddr, const void* g) {
    asm volatile("cp.async.cg.shared.global [%0], [%1], 16;" :: "r"(saddr), "l"(g));
}
__device__ __forceinline__ void cp_commit() { asm volatile("cp.async.commit_group;" ::: "memory"); }

__device__ __forceinline__ void split1(float v, __nv_bfloat16& h, __nv_bfloat16& l) {
    h = __float2bfloat16(v);
    l = __float2bfloat16(v - __bfloat162float(h));
}
__device__ __forceinline__ void split_pack(float a, float b, __nv_bfloat162& hi2, __nv_bfloat162& lo2) {
    __nv_bfloat16 ha, la, hb, lb;
    split1(a, ha, la); split1(b, hb, lb);
    hi2.x = ha; hi2.y = hb;
    lo2.x = la; lo2.y = lb;
}

// ---------------- unified bf16-split tensor-core GEMM, 4-stage pipeline ----------------
// C[M,N] = (A0(+A1))[M,K] @ (B0(+B1))[K,N]     ldb = ldc = NN
// EPI 1 = stacked QKV projection epilogue (V stored fp32)
// EPI 2 = transform (+bias, BN stats)
// EPI 3 = xr->d: d = aux(x) - acc/(1e-9+colsum[col]), split store
#define SA_STRIDE 24
#define SB_STRIDE 136

template<int NA, int NB, int EPI, int MINB>
__global__ __launch_bounds__(256, MINB)
void mma_gemm_kernel(const __nv_bfloat16* __restrict__ Ahi, const __nv_bfloat16* __restrict__ Alo,
                     int lda, size_t aBS,
                     const __nv_bfloat16* __restrict__ B0, const __nv_bfloat16* __restrict__ B1,
                     size_t bBS,
                     float* __restrict__ C, size_t cBS, int K,
                     const float* __restrict__ bias,
                     const float* __restrict__ aux, size_t auxBS)
{
    extern __shared__ __align__(16) char dynsm[];
    constexpr uint32_t A_PLANE = 128 * SA_STRIDE * 2;          // 6144
    constexpr uint32_t B_PLANE = 16 * SB_STRIDE * 2;           // 4352
    constexpr uint32_t STAGE   = NA * A_PLANE + NB * B_PLANE;

    const int bz = blockIdx.z;
    Ahi += (size_t)bz * aBS;
    if (NA == 2) Alo += (size_t)bz * aBS;
    B0  += (size_t)bz * bBS;
    if (NB == 2) B1 += (size_t)bz * bBS;
    C += (size_t)bz * cBS;
    if (EPI == 3) aux += (size_t)bz * auxBS;

    const int row0 = blockIdx.y * 128;
    const int col0 = blockIdx.x * 128;
    const int tid  = threadIdx.x;
    const int lane = tid & 31, warp = tid >> 5;
    const int wm = warp & 3;
    const int wn = warp >> 2;

    const int ar = tid >> 1, ac = (tid & 1) * 8;
    const int bk = tid >> 4, bc = (tid & 15) * 8;
    const size_t gA = (size_t)(row0 + ar) * lda + ac;
    const size_t gB = (size_t)bk * NN + col0 + bc;

    const uint32_t sbase = (uint32_t)__cvta_generic_to_shared(dynsm);
    const uint32_t sAst = (uint32_t)(ar * SA_STRIDE + ac) * 2;
    const uint32_t sBst = NA * A_PLANE + (uint32_t)(bk * SB_STRIDE + bc) * 2;

    float acc[2][8][4];
#pragma unroll
    for (int i = 0; i < 2; i++)
#pragma unroll
        for (int j = 0; j < 8; j++)
#pragma unroll
            for (int k = 0; k < 4; k++) acc[i][j][k] = 0.f;

    const int KT = K >> 4;

    auto issue = [&](int kt, int s) {
        const size_t ka = gA + (size_t)kt * 16;
        const size_t kb = gB + (size_t)kt * 16 * NN;
        const uint32_t st = sbase + (uint32_t)s * STAGE;
        cpasync16(st + sAst, Ahi + ka);
        if (NA == 2) cpasync16(st + A_PLANE + sAst, Alo + ka);
        cpasync16(st + sBst, B0 + kb);
        if (NB == 2) cpasync16(st + B_PLANE + sBst, B1 + kb);
    };

#pragma unroll
    for (int s = 0; s < 3; s++) { issue(s, s); cp_commit(); }

    const int lr = lane & 15, lc8 = (lane >> 4) * 8;
    const uint32_t aOff = ((wm * 32 + lr) * SA_STRIDE + lc8) * 2;
    const uint32_t bOff = NA * A_PLANE + (lr * SB_STRIDE + wn * 64 + lc8) * 2;

    for (int kt = 0; kt < KT; kt++) {
        asm volatile("cp.async.wait_group 2;" ::: "memory");
        __syncthreads();
        if (kt + 3 < KT) issue(kt + 3, (kt + 3) & 3);
        cp_commit();

        const uint32_t st = sbase + (uint32_t)(kt & 3) * STAGE;

        uint32_t ah[2][4], al[2][4];
#pragma unroll
        for (int mi = 0; mi < 2; mi++) {
            ldsm4(ah[mi], st + aOff + mi * 16 * SA_STRIDE * 2);
            if (NA == 2) ldsm4(al[mi], st + A_PLANE + aOff + mi * 16 * SA_STRIDE * 2);
        }
        uint32_t bh[4][4], bl[4][4];
#pragma unroll
        for (int j = 0; j < 4; j++) {
            ldsm4t(bh[j], st + bOff + j * 16 * 2);
            if (NB == 2) ldsm4t(bl[j], st + bOff + B_PLANE + j * 16 * 2);
        }
#pragma unroll
        for (int mi = 0; mi < 2; mi++) {
#pragma unroll
            for (int j = 0; j < 4; j++) {
                mma16816(acc[mi][2 * j],     ah[mi], &bh[j][0]);
                mma16816(acc[mi][2 * j + 1], ah[mi], &bh[j][2]);
                if (NB == 2) {
                    mma16816(acc[mi][2 * j],     ah[mi], &bl[j][0]);
                    mma16816(acc[mi][2 * j + 1], ah[mi], &bl[j][2]);
                }
                if (NA == 2) {
                    mma16816(acc[mi][2 * j],     al[mi], &bh[j][0]);
                    mma16816(acc[mi][2 * j + 1], al[mi], &bh[j][2]);
                }
            }
        }
    }

    const int gid = lane >> 2, t4 = lane & 3;

    if (EPI == 1) {
        const int by = blockIdx.y;
#pragma unroll
        for (int mi = 0; mi < 2; mi++)
#pragma unroll
            for (int nj = 0; nj < 8; nj++) {
                const int r = row0 + wm * 32 + mi * 16 + gid;
                const int col = col0 + wn * 64 + nj * 8 + t4 * 2;
                const float v00 = acc[mi][nj][0], v01 = acc[mi][nj][1];
                const float v10 = acc[mi][nj][2], v11 = acc[mi][nj][3];
                if (by == 0) {
                    if (r < 64) {  // Q -> transposed split [n][o]
                        const size_t base = (size_t)bz * NN * CQ;
                        __nv_bfloat16 h, l;
                        split1(v00, h, l); g_Qthi[base + (size_t)col * CQ + r] = h;       g_Qtlo[base + (size_t)col * CQ + r] = l;
                        split1(v01, h, l); g_Qthi[base + (size_t)(col + 1) * CQ + r] = h; g_Qtlo[base + (size_t)(col + 1) * CQ + r] = l;
                        split1(v10, h, l); g_Qthi[base + (size_t)col * CQ + r + 8] = h;       g_Qtlo[base + (size_t)col * CQ + r + 8] = l;
                        split1(v11, h, l); g_Qthi[base + (size_t)(col + 1) * CQ + r + 8] = h; g_Qtlo[base + (size_t)(col + 1) * CQ + r + 8] = l;
                    } else {       // K -> split [o][n]
                        const int kr = r - 64;
                        const size_t base = (size_t)bz * CQ * NN;
                        __nv_bfloat162 h2, l2;
                        split_pack(v00, v01, h2, l2);
                        *(__nv_bfloat162*)&g_Khi[base + (size_t)kr * NN + col] = h2;
                        *(__nv_bfloat162*)&g_Klo[base + (size_t)kr * NN + col] = l2;
                        split_pack(v10, v11, h2, l2);
                        *(__nv_bfloat162*)&g_Khi[base + (size_t)(kr + 8) * NN + col] = h2;
                        *(__nv_bfloat162*)&g_Klo[base + (size_t)(kr + 8) * NN + col] = l2;
                    }
                } else {           // V rows (+bias) -> fp32 (single rounding happens in vrescale)
                    const int vr = r - 128;
                    float* dst = g_V + (size_t)bz * CC * NN;
                    const float b0 = bias[vr], b1 = bias[vr + 8];
                    *(float2*)&dst[(size_t)vr * NN + col]       = make_float2(v00 + b0, v01 + b0);
                    *(float2*)&dst[(size_t)(vr + 8) * NN + col] = make_float2(v10 + b1, v11 + b1);
                }
            }
    }

    if (EPI == 2) {
        float ssum[2][2] = {{0.f, 0.f}, {0.f, 0.f}};
        float ssq[2][2]  = {{0.f, 0.f}, {0.f, 0.f}};
#pragma unroll
        for (int mi = 0; mi < 2; mi++)
#pragma unroll
            for (int nj = 0; nj < 8; nj++) {
                const int r = row0 + wm * 32 + mi * 16 + gid;
                const int col = col0 + wn * 64 + nj * 8 + t4 * 2;
                const float b0 = bias[r], b1 = bias[r + 8];
                const float v00 = acc[mi][nj][0] + b0, v01 = acc[mi][nj][1] + b0;
                const float v10 = acc[mi][nj][2] + b1, v11 = acc[mi][nj][3] + b1;
                *(float2*)&C[(size_t)r * NN + col]       = make_float2(v00, v01);
                *(float2*)&C[(size_t)(r + 8) * NN + col] = make_float2(v10, v11);
                ssum[mi][0] += v00 + v01;  ssq[mi][0] += v00 * v00 + v01 * v01;
                ssum[mi][1] += v10 + v11;  ssq[mi][1] += v10 * v10 + v11 * v11;
            }
#pragma unroll
        for (int mi = 0; mi < 2; mi++)
#pragma unroll
            for (int h = 0; h < 2; h++) {
                const int r = row0 + wm * 32 + mi * 16 + gid + h * 8;
                atomicAdd(&g_sum[r], ssum[mi][h]);
                atomicAdd(&g_sumsq[r], ssq[mi][h]);
            }
    }

    if (EPI == 3) {
#pragma unroll
        for (int mi = 0; mi < 2; mi++)
#pragma unroll
            for (int nj = 0; nj < 8; nj++) {
                const int r = row0 + wm * 32 + mi * 16 + gid;
                const int col = col0 + wn * 64 + nj * 8 + t4 * 2;
                const float cs0 = 1.0f / (1e-9f + g_colsum[bz * NN + col]);
                const float cs1 = 1.0f / (1e-9f + g_colsum[bz * NN + col + 1]);
                const size_t base = (size_t)bz * CC * NN;
                const float d00 = aux[(size_t)r * NN + col]       - acc[mi][nj][0] * cs0;
                const float d01 = aux[(size_t)r * NN + col + 1]   - acc[mi][nj][1] * cs1;
                const float d10 = aux[(size_t)(r + 8) * NN + col]     - acc[mi][nj][2] * cs0;
                const float d11 = aux[(size_t)(r + 8) * NN + col + 1] - acc[mi][nj][3] * cs1;
                __nv_bfloat162 h2, l2;
                split_pack(d00, d01, h2, l2);
                *(__nv_bfloat162*)&g_dhi[base + (size_t)r * NN + col] = h2;
                *(__nv_bfloat162*)&g_dlo[base + (size_t)r * NN + col] = l2;
                split_pack(d10, d11, h2, l2);
                *(__nv_bfloat162*)&g_dhi[base + (size_t)(r + 8) * NN + col] = h2;
                *(__nv_bfloat162*)&g_dlo[base + (size_t)(r + 8) * NN + col] = l2;
            }
    }
}

// ---------------- fused energy + exp + rowsum -> U bf16 ----------------
#define QA_ST 72
#define KB_ST 136

__global__ __launch_bounds__(256)
void attn_kernel()
{
    extern __shared__ __align__(16) char dsm[];
    __nv_bfloat16* sQ = (__nv_bfloat16*)dsm;
    __nv_bfloat16* sK = sQ + 2 * 128 * QA_ST;
    float* s_rs = (float*)(sK + 2 * 2 * 64 * KB_ST);

    const int cg = blockIdx.x;          // column group: 4 tiles of 128 = 512 cols
    const int b  = blockIdx.z;
    const int r0 = blockIdx.y * 128;
    const int tid = threadIdx.x;
    const int lane = tid & 31, warp = tid >> 5;
    const int wm = warp & 3, wn = warp >> 2;

    if (tid < 128) s_rs[tid] = 0.f;

    const uint32_t sQb = (uint32_t)__cvta_generic_to_shared(sQ);
    const uint32_t sKb = (uint32_t)__cvta_generic_to_shared(sK);

    const __nv_bfloat16* Qhi = g_Qthi + (size_t)b * NN * CQ;
    const __nv_bfloat16* Qlo = g_Qtlo + (size_t)b * NN * CQ;
#pragma unroll
    for (int p = 0; p < 4; p++) {
        const int idx = p * 256 + tid;
        const int row = idx >> 3, c8 = (idx & 7) * 8;
        cpasync16(sQb + (uint32_t)(row * QA_ST + c8) * 2,
                  Qhi + (size_t)(r0 + row) * CQ + c8);
        cpasync16(sQb + (uint32_t)(128 * QA_ST + row * QA_ST + c8) * 2,
                  Qlo + (size_t)(r0 + row) * CQ + c8);
    }
    cp_commit();

    const __nv_bfloat16* Khi = g_Khi + (size_t)b * CQ * NN;
    const __nv_bfloat16* Klo = g_Klo + (size_t)b * CQ * NN;
    const int kr = tid >> 4, kc8 = (tid & 15) * 8;

    auto issueK = [&](int tile, int stage) {
        const int c0 = (cg * 4 + tile) * 128;
        const uint32_t base = sKb + (uint32_t)stage * (2 * 64 * KB_ST * 2);
#pragma unroll
        for (int c = 0; c < 4; c++) {
            const int r = kr + c * 16;
            cpasync16(base + (uint32_t)(r * KB_ST + kc8) * 2,
                      Khi + (size_t)r * NN + c0 + kc8);
            cpasync16(base + (uint32_t)(64 * KB_ST + r * KB_ST + kc8) * 2,
                      Klo + (size_t)r * NN + c0 + kc8);
        }
        cp_commit();
    };

    issueK(0, 0);

    const int lr = lane & 15, lc8 = (lane >> 4) * 8;
    const uint32_t aBase = sQb + (uint32_t)((wm * 32 + lr) * QA_ST + lc8) * 2;
    const uint32_t bBase = sKb + (uint32_t)(lr * KB_ST + wn * 64 + lc8) * 2;
    constexpr uint32_t QPLANE = 128 * QA_ST * 2;
    constexpr uint32_t KPLANE = 64 * KB_ST * 2;
    constexpr uint32_t KSTAGE = 2 * KPLANE;

    const int gid = lane >> 2, t4 = lane & 3;
    float rowsum[2][2] = {{0.f, 0.f}, {0.f, 0.f}};
    __nv_bfloat16* U = g_A + (size_t)b * NN * NN;

    for (int tile = 0; tile < 4; tile++) {
        const int cur = tile & 1;
        if (tile + 1 < 4) {
            issueK(tile + 1, cur ^ 1);
            asm volatile("cp.async.wait_group 1;" ::: "memory");
        } else {
            asm volatile("cp.async.wait_group 0;" ::: "memory");
        }
        __syncthreads();

        const uint32_t bS = cur * KSTAGE;

        float acc[2][8][4];
#pragma unroll
        for (int i = 0; i < 2; i++)
#pragma unroll
            for (int j = 0; j < 8; j++)
#pragma unroll
                for (int k = 0; k < 4; k++) acc[i][j][k] = 0.f;

#pragma unroll
        for (int ch = 0; ch < 4; ch++) {
            uint32_t ah[2][4], al[2][4];
#pragma unroll
            for (int mi = 0; mi < 2; mi++) {
                ldsm4(ah[mi], aBase + ch * 32 + mi * 16 * QA_ST * 2);
                ldsm4(al[mi], aBase + QPLANE + ch * 32 + mi * 16 * QA_ST * 2);
            }
            uint32_t bh[4][4], bl[4][4];
#pragma unroll
            for (int j = 0; j < 4; j++) {
                ldsm4t(bh[j], bBase + bS + ch * 16 * KB_ST * 2 + j * 16 * 2);
                ldsm4t(bl[j], bBase + bS + KPLANE + ch * 16 * KB_ST * 2 + j * 16 * 2);
            }
#pragma unroll
            for (int mi = 0; mi < 2; mi++)
#pragma unroll
                for (int j = 0; j < 4; j++) {
                    mma16816(acc[mi][2 * j],     ah[mi], &bh[j][0]);
                    mma16816(acc[mi][2 * j + 1], ah[mi], &bh[j][2]);
                    mma16816(acc[mi][2 * j],     ah[mi], &bl[j][0]);
                    mma16816(acc[mi][2 * j + 1], ah[mi], &bl[j][2]);
                    mma16816(acc[mi][2 * j],     al[mi], &bh[j][0]);
                    mma16816(acc[mi][2 * j + 1], al[mi], &bh[j][2]);
                }
        }

        const int c0 = (cg * 4 + tile) * 128;
#pragma unroll
        for (int mi = 0; mi < 2; mi++)
#pragma unroll
            for (int nj = 0; nj < 8; nj++) {
                const int row = r0 + wm * 32 + mi * 16 + gid;
                const int col = c0 + wn * 64 + nj * 8 + t4 * 2;
                const float e00 = __expf(acc[mi][nj][0]);
                const float e01 = __expf(acc[mi][nj][1]);
                const float e10 = __expf(acc[mi][nj][2]);
                const float e11 = __expf(acc[mi][nj][3]);
                rowsum[mi][0] += e00 + e01;
                rowsum[mi][1] += e10 + e11;
                __nv_bfloat162 p0, p1;
                p0.x = __float2bfloat16(e00); p0.y = __float2bfloat16(e01);
                p1.x = __float2bfloat16(e10); p1.y = __float2bfloat16(e11);
                *(__nv_bfloat162*)&U[(size_t)row * NN + col] = p0;
                *(__nv_bfloat162*)&U[(size_t)(row + 8) * NN + col] = p1;
            }
        __syncthreads();
    }

#pragma unroll
    for (int mi = 0; mi < 2; mi++)
#pragma unroll
        for (int h = 0; h < 2; h++) {
            float v = rowsum[mi][h];
            v += __shfl_xor_sync(0xffffffffu, v, 1);
            v += __shfl_xor_sync(0xffffffffu, v, 2);
            if (t4 == 0) atomicAdd(&s_rs[wm * 32 + mi * 16 + gid + h * 8], v);
        }
    __syncthreads();
    if (tid < 128) g_rspart[(size_t)cg * BB * NN + b * NN + r0 + tid] = s_rs[tid];
}

// ---------------- invrs: reduce 8 rowsum partials ----------------
__global__ void invrs_kernel()
{
    const int i = blockIdx.x * 256 + threadIdx.x;   // over BB*NN
    float s = 0.f;
#pragma unroll
    for (int p = 0; p < 8; p++) s += g_rspart[(size_t)p * BB * NN + i];
    g_invrs[i] = 1.0f / s;
}

// ---------------- V' = V_fp32 * invrs[n] -> single bf16 plane ----------------
__global__ void vrescale_kernel()
{
    const int b = blockIdx.z;
    const size_t i4 = (size_t)blockIdx.x * 256 + threadIdx.x;   // over CC*NN/4
    const float4 v = ((const float4*)(g_V + (size_t)b * CC * NN))[i4];
    const int n4 = (int)((i4 * 4) & (NN - 1));
    const float4 w = *(const float4*)&g_invrs[b * NN + n4];
    __nv_bfloat162 p0, p1;
    p0.x = __float2bfloat16(v.x * w.x); p0.y = __float2bfloat16(v.y * w.y);
    p1.x = __float2bfloat16(v.z * w.z); p1.y = __float2bfloat16(v.w * w.w);
    uint2 o;
    o.x = *(uint32_t*)&p0; o.y = *(uint32_t*)&p1;
    ((uint2*)(g_Vhi + (size_t)b * CC * NN))[i4] = o;
}

// ---------------- weighted column sums (uint4 vectorized, invrs staged in smem) ----------------
__global__ void colsum_kernel()
{
    __shared__ float sw[128];
    const int b  = blockIdx.z;
    const int n0 = blockIdx.y * 128;
    const int m8 = blockIdx.x * 256 + threadIdx.x;   // uint4 index; covers 8 columns
    if (threadIdx.x < 128) sw[threadIdx.x] = g_invrs[b * NN + n0 + threadIdx.x];
    __syncthreads();

    const uint4* A4 = (const uint4*)(g_A + (size_t)b * NN * NN);
    float s[8];
#pragma unroll
    for (int j = 0; j < 8; j++) s[j] = 0.f;

#pragma unroll 4
    for (int n = 0; n < 128; n++) {
        const uint4 v = A4[(size_t)(n0 + n) * (NN / 8) + m8];
        const float w = sw[n];
        const __nv_bfloat162 p0 = *(const __nv_bfloat162*)&v.x;
        const __nv_bfloat162 p1 = *(const __nv_bfloat162*)&v.y;
        const __nv_bfloat162 p2 = *(const __nv_bfloat162*)&v.z;
        const __nv_bfloat162 p3 = *(const __nv_bfloat162*)&v.w;
        s[0] += w * __bfloat162float(p0.x);  s[1] += w * __bfloat162float(p0.y);
        s[2] += w * __bfloat162float(p1.x);  s[3] += w * __bfloat162float(p1.y);
        s[4] += w * __bfloat162float(p2.x);  s[5] += w * __bfloat162float(p2.y);
        s[6] += w * __bfloat162float(p3.x);  s[7] += w * __bfloat162float(p3.y);
    }
#pragma unroll
    for (int j = 0; j < 8; j++)
        atomicAdd(&g_colsum[b * NN + m8 * 8 + j], s[j]);
}

// ---------------- splits ----------------
__global__ void split4_kernel(const float* __restrict__ src, size_t srcBS,
                              __nv_bfloat16* __restrict__ hi, __nv_bfloat16* __restrict__ lo,
                              size_t dstBS)
{
    const size_t i4 = (size_t)blockIdx.x * 256 + threadIdx.x;
    const float4 v = ((const float4*)(src + (size_t)blockIdx.z * srcBS))[i4];
    __nv_bfloat162 ha, la, hb, lb;
    split_pack(v.x, v.y, ha, la);
    split_pack(v.z, v.w, hb, lb);
    uint2 hv, lv;
    hv.x = *(uint32_t*)&ha; hv.y = *(uint32_t*)&hb;
    lv.x = *(uint32_t*)&la; lv.y = *(uint32_t*)&lb;
    ((uint2*)(hi + (size_t)blockIdx.z * dstBS))[i4] = hv;
    ((uint2*)(lo + (size_t)blockIdx.z * dstBS))[i4] = lv;
}

__global__ void wqkv_split_kernel(const float* __restrict__ Wq, const float* __restrict__ Wk,
                                  const float* __restrict__ Wv)
{
    const int t = blockIdx.x * 256 + threadIdx.x;
    float v;
    if (t < 64 * CC) v = Wq[t];
    else if (t < 128 * CC) v = Wk[t - 64 * CC];
    else v = Wv[t - 128 * CC];
    __nv_bfloat16 h, l;
    split1(v, h, l);
    g_Wqkvhi[t] = h; g_Wqkvlo[t] = l;
}

// ---------------- misc ----------------
__global__ void zero_kernel()
{
    const int t = blockIdx.x * 256 + threadIdx.x;
    if (t < CC) { g_sum[t] = 0.f; g_sumsq[t] = 0.f; }
    if (t < BB * NN) g_colsum[t] = 0.f;
}

// final: inline BN (each block spans exactly one channel since NN = 2^12)
__global__ void final_kernel(const float* __restrict__ x,
                             const float* __restrict__ gamma, const float* __restrict__ beta,
                             float* __restrict__ out)
{
    const size_t idx = (size_t)blockIdx.x * 256 + threadIdx.x;
    const int c = (int)((idx >> 12) & (CC - 1));
    const float cnt = (float)(BB * NN);
    const float mean = g_sum[c] / cnt;
    const float var = g_sumsq[c] / cnt - mean * mean;
    const float sc = gamma[c] * rsqrtf(var + 1e-5f);
    const float sh = beta[c] - mean * sc;
    const float t = g_T[idx] * sc + sh;
    out[idx] = x[idx] + fmaxf(t, 0.f);
}

// ---------------- launch ----------------
extern "C" void kernel_launch(void* const* d_in, const int* in_sizes, int n_in,
                              void* d_out, int out_size)
{
    const float* x     = (const float*)d_in[0];
    const float* Wq    = (const float*)d_in[1];
    const float* Wk    = (const float*)d_in[2];
    const float* Wv    = (const float*)d_in[3];
    const float* bv    = (const float*)d_in[4];
    const float* Wt    = (const float*)d_in[5];
    const float* bt    = (const float*)d_in[6];
    const float* gamma = (const float*)d_in[7];
    const float* beta  = (const float*)d_in[8];
    float* out = (float*)d_out;

    float *pT;
    __nv_bfloat16 *pA, *pXhi, *pXlo, *pVhi, *pDhi, *pDlo;
    __nv_bfloat16 *pWqkvhi, *pWqkvlo, *pWthi, *pWtlo;
    cudaGetSymbolAddress((void**)&pT, g_T);
    cudaGetSymbolAddress((void**)&pA, g_A);
    cudaGetSymbolAddress((void**)&pXhi, g_xhi);
    cudaGetSymbolAddress((void**)&pXlo, g_xlo);
    cudaGetSymbolAddress((void**)&pVhi, g_Vhi);
    cudaGetSymbolAddress((void**)&pDhi, g_dhi);
    cudaGetSymbolAddress((void**)&pDlo, g_dlo);
    cudaGetSymbolAddress((void**)&pWqkvhi, g_Wqkvhi);
    cudaGetSymbolAddress((void**)&pWqkvlo, g_Wqkvlo);
    cudaGetSymbolAddress((void**)&pWthi, g_Wthi);
    cudaGetSymbolAddress((void**)&pWtlo, g_Wtlo);

    const int attn_smem = (2 * 128 * QA_ST + 2 * 2 * 64 * KB_ST) * 2 + 128 * 4;
    cudaFuncSetAttribute(attn_kernel, cudaFuncAttributeMaxDynamicSharedMemorySize, attn_smem);

    const int smem_22 = 4 * (2 * 128 * SA_STRIDE * 2 + 2 * 16 * SB_STRIDE * 2);  // 83968
    const int smem_11 = 4 * (1 * 128 * SA_STRIDE * 2 + 1 * 16 * SB_STRIDE * 2);  // 41984
    cudaFuncSetAttribute(mma_gemm_kernel<2, 2, 1, 1>, cudaFuncAttributeMaxDynamicSharedMemorySize, smem_22);
    cudaFuncSetAttribute(mma_gemm_kernel<2, 2, 2, 1>, cudaFuncAttributeMaxDynamicSharedMemorySize, smem_22);
    cudaFuncSetAttribute(mma_gemm_kernel<1, 1, 3, 2>, cudaFuncAttributeMaxDynamicSharedMemorySize, smem_11);

    zero_kernel<<<BB * NN / 256, 256>>>();
    wqkv_split_kernel<<<384 * CC / 256, 256>>>(Wq, Wk, Wv);
    split4_kernel<<<dim3(CC * CC / 1024, 1, 1), 256>>>(Wt, 0, pWthi, pWtlo, 0);
    split4_kernel<<<dim3(CC * NN / 1024, 1, BB), 256>>>(x, (size_t)CC * NN, pXhi, pXlo, (size_t)CC * NN);

    // stacked QKV projection: [384,256] @ [256,4096]; epilogue writes Qt/K splits + V fp32
    mma_gemm_kernel<2, 2, 1, 1><<<dim3(NN / 128, 3, BB), 256, smem_22>>>(
        pWqkvhi, pWqkvlo, CC, 0,
        pXhi, pXlo, (size_t)CC * NN,
        pT /*unused*/, 0, CC, bv, nullptr, 0);

    // fused energy + exp + rowsum -> U (bf16), rowsum partials (column-split grid)
    attn_kernel<<<dim3(8, NN / 128, BB), 256, attn_smem>>>();

    // invrs = 1 / sum of 8 partials
    invrs_kernel<<<BB * NN / 256, 256>>>();

    // V' = V_fp32 * invrs[n] -> single bf16 plane
    vrescale_kernel<<<dim3(CC * NN / 1024, 1, BB), 256>>>();

    // weighted column sums for L1 renorm (vectorized)
    colsum_kernel<<<dim3(NN / 2048, NN / 128, BB), 256>>>();

    // x_r = V' @ U (single-product); epilogue computes d = x - xr*colscale, writes d splits
    mma_gemm_kernel<1, 1, 3, 2><<<dim3(NN / 128, CC / 128, BB), 256, smem_11>>>(
        pVhi, nullptr, NN, (size_t)CC * NN,
        pA, nullptr, (size_t)NN * NN,
        pT /*unused*/, 0, NN, nullptr, x, (size_t)CC * NN);

    // t = Wt @ d + bt, with BN stats -> g_T
    mma_gemm_kernel<2, 2, 2, 1><<<dim3(NN / 128, CC / 128, BB), 256, smem_22>>>(
        pWthi, pWtlo, CC, 0,
        pDhi, pDlo, (size_t)CC * NN,
        pT, (size_t)CC * NN, CC, bt, nullptr, 0);

    // final with inline BN (replaces bn_finalize + old final)
    final_kernel<<<(size_t)BB * CC * NN / 256, 256>>>(x, gamma, beta, out);
}

// round 14
// speedup vs baseline: 1.0642x; 1.0100x over previous
#include <cuda_runtime.h>
#include <cuda_bf16.h>
#include <cstdint>

#define BB 4
#define CC 256
#define CQ 64
#define NN 4096

// ---------------- scratch (device globals; no allocations) ----------------
__device__ __nv_bfloat16 g_A[(size_t)BB * NN * NN];     // U = exp(E), bf16, unnormalized
__device__ __nv_bfloat16 g_xhi[(size_t)BB * CC * NN];
__device__ __nv_bfloat16 g_xlo[(size_t)BB * CC * NN];
__device__ float g_V[(size_t)BB * CC * NN];             // V fp32 (pre-rescale)
__device__ __nv_bfloat16 g_Vhi[(size_t)BB * CC * NN];   // V' = V*invrs, single bf16 plane
__device__ __nv_bfloat16 g_dhi[(size_t)BB * CC * NN];   // d = x - xr*colscale, split
__device__ __nv_bfloat16 g_dlo[(size_t)BB * CC * NN];
__device__ __nv_bfloat16 g_Qthi[(size_t)BB * NN * CQ];  // Q transposed [n][o]
__device__ __nv_bfloat16 g_Qtlo[(size_t)BB * NN * CQ];
__device__ __nv_bfloat16 g_Khi[(size_t)BB * CQ * NN];
__device__ __nv_bfloat16 g_Klo[(size_t)BB * CQ * NN];
__device__ __nv_bfloat16 g_Wqkvhi[384 * CC];            // Wq(64) ; Wk(64) ; Wv(256) rows
__device__ __nv_bfloat16 g_Wqkvlo[384 * CC];
__device__ __nv_bfloat16 g_Wthi[CC * CC];
__device__ __nv_bfloat16 g_Wtlo[CC * CC];
__device__ float g_T[(size_t)BB * CC * NN];
__device__ float g_rspart[8 * BB * NN];                 // per-colgroup rowsum partials
__device__ float g_invrs[BB * NN];                      // 1 / softmax row sums
__device__ float g_colsum[BB * NN];
__device__ float g_sum[CC];
__device__ float g_sumsq[CC];

// ---------------- PTX helpers ----------------
__device__ __forceinline__ void mma16816(float* c, const uint32_t* a, const uint32_t* b) {
    asm volatile(
        "mma.sync.aligned.m16n8k16.row.col.f32.bf16.bf16.f32 "
        "{%0,%1,%2,%3}, {%4,%5,%6,%7}, {%8,%9}, {%0,%1,%2,%3};\n"
        : "+f"(c[0]), "+f"(c[1]), "+f"(c[2]), "+f"(c[3])
        : "r"(a[0]), "r"(a[1]), "r"(a[2]), "r"(a[3]), "r"(b[0]), "r"(b[1]));
}
__device__ __forceinline__ void ldsm4(uint32_t* r, uint32_t addr) {
    asm volatile("ldmatrix.sync.aligned.m8n8.x4.shared.b16 {%0,%1,%2,%3}, [%4];"
        : "=r"(r[0]), "=r"(r[1]), "=r"(r[2]), "=r"(r[3]) : "r"(addr));
}
__device__ __forceinline__ void ldsm4t(uint32_t* r, uint32_t addr) {
    asm volatile("ldmatrix.sync.aligned.m8n8.x4.trans.shared.b16 {%0,%1,%2,%3}, [%4];"
        : "=r"(r[0]), "=r"(r[1]), "=r"(r[2]), "=r"(r[3]) : "r"(addr));
}
__device__ __forceinline__ void cpasync16(uint32_t saddr, const void* g) {
    asm volatile("cp.async.cg.shared.global [%0], [%1], 16;" :: "r"(saddr), "l"(g));
}
__device__ __forceinline__ void cp_commit() { asm volatile("cp.async.commit_group;" ::: "memory"); }

__device__ __forceinline__ void split1(float v, __nv_bfloat16& h, __nv_bfloat16& l) {
    h = __float2bfloat16(v);
    l = __float2bfloat16(v - __bfloat162float(h));
}
__device__ __forceinline__ void split_pack(float a, float b, __nv_bfloat162& hi2, __nv_bfloat162& lo2) {
    __nv_bfloat16 ha, la, hb, lb;
    split1(a, ha, la); split1(b, hb, lb);
    hi2.x = ha; hi2.y = hb;
    lo2.x = la; lo2.y = lb;
}

// ---------------- unified bf16-split tensor-core GEMM, 4-stage pipeline ----------------
// C[M,N] = (A0(+A1))[M,K] @ (B0(+B1))[K,N]     ldb = ldc = NN
// EPI 1 = stacked QKV projection epilogue (V stored fp32)
// EPI 2 = transform (+bias, BN stats)
// EPI 3 = xr->d: d = aux(x) - acc/(1e-9+colsum[col]), split store
#define SA_STRIDE 24
#define SB_STRIDE 136

template<int NA, int NB, int EPI>
__global__ __launch_bounds__(256)
void mma_gemm_kernel(const __nv_bfloat16* __restrict__ Ahi, const __nv_bfloat16* __restrict__ Alo,
                     int lda, size_t aBS,
                     const __nv_bfloat16* __restrict__ B0, const __nv_bfloat16* __restrict__ B1,
                     size_t bBS,
                     float* __restrict__ C, size_t cBS, int K,
                     const float* __restrict__ bias,
                     const float* __restrict__ aux, size_t auxBS)
{
    extern __shared__ __align__(16) char dynsm[];
    constexpr uint32_t A_PLANE = 128 * SA_STRIDE * 2;          // 6144
    constexpr uint32_t B_PLANE = 16 * SB_STRIDE * 2;           // 4352
    constexpr uint32_t STAGE   = NA * A_PLANE + NB * B_PLANE;

    const int bz = blockIdx.z;
    Ahi += (size_t)bz * aBS;
    if (NA == 2) Alo += (size_t)bz * aBS;
    B0  += (size_t)bz * bBS;
    if (NB == 2) B1 += (size_t)bz * bBS;
    C += (size_t)bz * cBS;
    if (EPI == 3) aux += (size_t)bz * auxBS;

    const int row0 = blockIdx.y * 128;
    const int col0 = blockIdx.x * 128;
    const int tid  = threadIdx.x;
    const int lane = tid & 31, warp = tid >> 5;
    const int wm = warp & 3;
    const int wn = warp >> 2;

    const int ar = tid >> 1, ac = (tid & 1) * 8;
    const int bk = tid >> 4, bc = (tid & 15) * 8;
    const size_t gA = (size_t)(row0 + ar) * lda + ac;
    const size_t gB = (size_t)bk * NN + col0 + bc;

    const uint32_t sbase = (uint32_t)__cvta_generic_to_shared(dynsm);
    const uint32_t sAst = (uint32_t)(ar * SA_STRIDE + ac) * 2;
    const uint32_t sBst = NA * A_PLANE + (uint32_t)(bk * SB_STRIDE + bc) * 2;

    float acc[2][8][4];
#pragma unroll
    for (int i = 0; i < 2; i++)
#pragma unroll
        for (int j = 0; j < 8; j++)
#pragma unroll
            for (int k = 0; k < 4; k++) acc[i][j][k] = 0.f;

    const int KT = K >> 4;

    auto issue = [&](int kt, int s) {
        const size_t ka = gA + (size_t)kt * 16;
        const size_t kb = gB + (size_t)kt * 16 * NN;
        const uint32_t st = sbase + (uint32_t)s * STAGE;
        cpasync16(st + sAst, Ahi + ka);
        if (NA == 2) cpasync16(st + A_PLANE + sAst, Alo + ka);
        cpasync16(st + sBst, B0 + kb);
        if (NB == 2) cpasync16(st + B_PLANE + sBst, B1 + kb);
    };

#pragma unroll
    for (int s = 0; s < 3; s++) { issue(s, s); cp_commit(); }

    const int lr = lane & 15, lc8 = (lane >> 4) * 8;
    const uint32_t aOff = ((wm * 32 + lr) * SA_STRIDE + lc8) * 2;
    const uint32_t bOff = NA * A_PLANE + (lr * SB_STRIDE + wn * 64 + lc8) * 2;

    for (int kt = 0; kt < KT; kt++) {
        asm volatile("cp.async.wait_group 2;" ::: "memory");
        __syncthreads();
        if (kt + 3 < KT) issue(kt + 3, (kt + 3) & 3);
        cp_commit();

        const uint32_t st = sbase + (uint32_t)(kt & 3) * STAGE;

        uint32_t ah[2][4], al[2][4];
#pragma unroll
        for (int mi = 0; mi < 2; mi++) {
            ldsm4(ah[mi], st + aOff + mi * 16 * SA_STRIDE * 2);
            if (NA == 2) ldsm4(al[mi], st + A_PLANE + aOff + mi * 16 * SA_STRIDE * 2);
        }
        uint32_t bh[4][4], bl[4][4];
#pragma unroll
        for (int j = 0; j < 4; j++) {
            ldsm4t(bh[j], st + bOff + j * 16 * 2);
            if (NB == 2) ldsm4t(bl[j], st + bOff + B_PLANE + j * 16 * 2);
        }
#pragma unroll
        for (int mi = 0; mi < 2; mi++) {
#pragma unroll
            for (int j = 0; j < 4; j++) {
                mma16816(acc[mi][2 * j],     ah[mi], &bh[j][0]);
                mma16816(acc[mi][2 * j + 1], ah[mi], &bh[j][2]);
                if (NB == 2) {
                    mma16816(acc[mi][2 * j],     ah[mi], &bl[j][0]);
                    mma16816(acc[mi][2 * j + 1], ah[mi], &bl[j][2]);
                }
                if (NA == 2) {
                    mma16816(acc[mi][2 * j],     al[mi], &bh[j][0]);
                    mma16816(acc[mi][2 * j + 1], al[mi], &bh[j][2]);
                }
            }
        }
    }

    const int gid = lane >> 2, t4 = lane & 3;

    if (EPI == 1) {
        const int by = blockIdx.y;
#pragma unroll
        for (int mi = 0; mi < 2; mi++)
#pragma unroll
            for (int nj = 0; nj < 8; nj++) {
                const int r = row0 + wm * 32 + mi * 16 + gid;
                const int col = col0 + wn * 64 + nj * 8 + t4 * 2;
                const float v00 = acc[mi][nj][0], v01 = acc[mi][nj][1];
                const float v10 = acc[mi][nj][2], v11 = acc[mi][nj][3];
                if (by == 0) {
                    if (r < 64) {  // Q -> transposed split [n][o]
                        const size_t base = (size_t)bz * NN * CQ;
                        __nv_bfloat16 h, l;
                        split1(v00, h, l); g_Qthi[base + (size_t)col * CQ + r] = h;       g_Qtlo[base + (size_t)col * CQ + r] = l;
                        split1(v01, h, l); g_Qthi[base + (size_t)(col + 1) * CQ + r] = h; g_Qtlo[base + (size_t)(col + 1) * CQ + r] = l;
                        split1(v10, h, l); g_Qthi[base + (size_t)col * CQ + r + 8] = h;       g_Qtlo[base + (size_t)col * CQ + r + 8] = l;
                        split1(v11, h, l); g_Qthi[base + (size_t)(col + 1) * CQ + r + 8] = h; g_Qtlo[base + (size_t)(col + 1) * CQ + r + 8] = l;
                    } else {       // K -> split [o][n]
                        const int kr = r - 64;
                        const size_t base = (size_t)bz * CQ * NN;
                        __nv_bfloat162 h2, l2;
                        split_pack(v00, v01, h2, l2);
                        *(__nv_bfloat162*)&g_Khi[base + (size_t)kr * NN + col] = h2;
                        *(__nv_bfloat162*)&g_Klo[base + (size_t)kr * NN + col] = l2;
                        split_pack(v10, v11, h2, l2);
                        *(__nv_bfloat162*)&g_Khi[base + (size_t)(kr + 8) * NN + col] = h2;
                        *(__nv_bfloat162*)&g_Klo[base + (size_t)(kr + 8) * NN + col] = l2;
                    }
                } else {           // V rows (+bias) -> fp32 (single rounding happens in vrescale)
                    const int vr = r - 128;
                    float* dst = g_V + (size_t)bz * CC * NN;
                    const float b0 = bias[vr], b1 = bias[vr + 8];
                    *(float2*)&dst[(size_t)vr * NN + col]       = make_float2(v00 + b0, v01 + b0);
                    *(float2*)&dst[(size_t)(vr + 8) * NN + col] = make_float2(v10 + b1, v11 + b1);
                }
            }
    }

    if (EPI == 2) {
        float ssum[2][2] = {{0.f, 0.f}, {0.f, 0.f}};
        float ssq[2][2]  = {{0.f, 0.f}, {0.f, 0.f}};
#pragma unroll
        for (int mi = 0; mi < 2; mi++)
#pragma unroll
            for (int nj = 0; nj < 8; nj++) {
                const int r = row0 + wm * 32 + mi * 16 + gid;
                const int col = col0 + wn * 64 + nj * 8 + t4 * 2;
                const float b0 = bias[r], b1 = bias[r + 8];
                const float v00 = acc[mi][nj][0] + b0, v01 = acc[mi][nj][1] + b0;
                const float v10 = acc[mi][nj][2] + b1, v11 = acc[mi][nj][3] + b1;
                *(float2*)&C[(size_t)r * NN + col]       = make_float2(v00, v01);
                *(float2*)&C[(size_t)(r + 8) * NN + col] = make_float2(v10, v11);
                ssum[mi][0] += v00 + v01;  ssq[mi][0] += v00 * v00 + v01 * v01;
                ssum[mi][1] += v10 + v11;  ssq[mi][1] += v10 * v10 + v11 * v11;
            }
#pragma unroll
        for (int mi = 0; mi < 2; mi++)
#pragma unroll
            for (int h = 0; h < 2; h++) {
                const int r = row0 + wm * 32 + mi * 16 + gid + h * 8;
                atomicAdd(&g_sum[r], ssum[mi][h]);
                atomicAdd(&g_sumsq[r], ssq[mi][h]);
            }
    }

    if (EPI == 3) {
#pragma unroll
        for (int mi = 0; mi < 2; mi++)
#pragma unroll
            for (int nj = 0; nj < 8; nj++) {
                const int r = row0 + wm * 32 + mi * 16 + gid;
                const int col = col0 + wn * 64 + nj * 8 + t4 * 2;
                const float cs0 = 1.0f / (1e-9f + g_colsum[bz * NN + col]);
                const float cs1 = 1.0f / (1e-9f + g_colsum[bz * NN + col + 1]);
                const size_t base = (size_t)bz * CC * NN;
                const float d00 = aux[(size_t)r * NN + col]       - acc[mi][nj][0] * cs0;
                const float d01 = aux[(size_t)r * NN + col + 1]   - acc[mi][nj][1] * cs1;
                const float d10 = aux[(size_t)(r + 8) * NN + col]     - acc[mi][nj][2] * cs0;
                const float d11 = aux[(size_t)(r + 8) * NN + col + 1] - acc[mi][nj][3] * cs1;
                __nv_bfloat162 h2, l2;
                split_pack(d00, d01, h2, l2);
                *(__nv_bfloat162*)&g_dhi[base + (size_t)r * NN + col] = h2;
                *(__nv_bfloat162*)&g_dlo[base + (size_t)r * NN + col] = l2;
                split_pack(d10, d11, h2, l2);
                *(__nv_bfloat162*)&g_dhi[base + (size_t)(r + 8) * NN + col] = h2;
                *(__nv_bfloat162*)&g_dlo[base + (size_t)(r + 8) * NN + col] = l2;
            }
    }
}

// ---------------- fused energy + exp + rowsum -> U bf16 ----------------
#define QA_ST 72
#define KB_ST 136

__global__ __launch_bounds__(256)
void attn_kernel()
{
    extern __shared__ __align__(16) char dsm[];
    __nv_bfloat16* sQ = (__nv_bfloat16*)dsm;
    __nv_bfloat16* sK = sQ + 2 * 128 * QA_ST;
    float* s_rs = (float*)(sK + 2 * 2 * 64 * KB_ST);

    const int cg = blockIdx.x;          // column group: 4 tiles of 128 = 512 cols
    const int b  = blockIdx.z;
    const int r0 = blockIdx.y * 128;
    const int tid = threadIdx.x;
    const int lane = tid & 31, warp = tid >> 5;
    const int wm = warp & 3, wn = warp >> 2;

    if (tid < 128) s_rs[tid] = 0.f;

    const uint32_t sQb = (uint32_t)__cvta_generic_to_shared(sQ);
    const uint32_t sKb = (uint32_t)__cvta_generic_to_shared(sK);

    const __nv_bfloat16* Qhi = g_Qthi + (size_t)b * NN * CQ;
    const __nv_bfloat16* Qlo = g_Qtlo + (size_t)b * NN * CQ;
#pragma unroll
    for (int p = 0; p < 4; p++) {
        const int idx = p * 256 + tid;
        const int row = idx >> 3, c8 = (idx & 7) * 8;
        cpasync16(sQb + (uint32_t)(row * QA_ST + c8) * 2,
                  Qhi + (size_t)(r0 + row) * CQ + c8);
        cpasync16(sQb + (uint32_t)(128 * QA_ST + row * QA_ST + c8) * 2,
                  Qlo + (size_t)(r0 + row) * CQ + c8);
    }
    cp_commit();

    const __nv_bfloat16* Khi = g_Khi + (size_t)b * CQ * NN;
    const __nv_bfloat16* Klo = g_Klo + (size_t)b * CQ * NN;
    const int kr = tid >> 4, kc8 = (tid & 15) * 8;

    auto issueK = [&](int tile, int stage) {
        const int c0 = (cg * 4 + tile) * 128;
        const uint32_t base = sKb + (uint32_t)stage * (2 * 64 * KB_ST * 2);
#pragma unroll
        for (int c = 0; c < 4; c++) {
            const int r = kr + c * 16;
            cpasync16(base + (uint32_t)(r * KB_ST + kc8) * 2,
                      Khi + (size_t)r * NN + c0 + kc8);
            cpasync16(base + (uint32_t)(64 * KB_ST + r * KB_ST + kc8) * 2,
                      Klo + (size_t)r * NN + c0 + kc8);
        }
        cp_commit();
    };

    issueK(0, 0);

    const int lr = lane & 15, lc8 = (lane >> 4) * 8;
    const uint32_t aBase = sQb + (uint32_t)((wm * 32 + lr) * QA_ST + lc8) * 2;
    const uint32_t bBase = sKb + (uint32_t)(lr * KB_ST + wn * 64 + lc8) * 2;
    constexpr uint32_t QPLANE = 128 * QA_ST * 2;
    constexpr uint32_t KPLANE = 64 * KB_ST * 2;
    constexpr uint32_t KSTAGE = 2 * KPLANE;

    const int gid = lane >> 2, t4 = lane & 3;
    float rowsum[2][2] = {{0.f, 0.f}, {0.f, 0.f}};
    __nv_bfloat16* U = g_A + (size_t)b * NN * NN;

    for (int tile = 0; tile < 4; tile++) {
        const int cur = tile & 1;
        if (tile + 1 < 4) {
            issueK(tile + 1, cur ^ 1);
            asm volatile("cp.async.wait_group 1;" ::: "memory");
        } else {
            asm volatile("cp.async.wait_group 0;" ::: "memory");
        }
        __syncthreads();

        const uint32_t bS = cur * KSTAGE;

        float acc[2][8][4];
#pragma unroll
        for (int i = 0; i < 2; i++)
#pragma unroll
            for (int j = 0; j < 8; j++)
#pragma unroll
                for (int k = 0; k < 4; k++) acc[i][j][k] = 0.f;

#pragma unroll
        for (int ch = 0; ch < 4; ch++) {
            uint32_t ah[2][4], al[2][4];
#pragma unroll
            for (int mi = 0; mi < 2; mi++) {
                ldsm4(ah[mi], aBase + ch * 32 + mi * 16 * QA_ST * 2);
                ldsm4(al[mi], aBase + QPLANE + ch * 32 + mi * 16 * QA_ST * 2);
            }
            uint32_t bh[4][4], bl[4][4];
#pragma unroll
            for (int j = 0; j < 4; j++) {
                ldsm4t(bh[j], bBase + bS + ch * 16 * KB_ST * 2 + j * 16 * 2);
                ldsm4t(bl[j], bBase + bS + KPLANE + ch * 16 * KB_ST * 2 + j * 16 * 2);
            }
#pragma unroll
            for (int mi = 0; mi < 2; mi++)
#pragma unroll
                for (int j = 0; j < 4; j++) {
                    mma16816(acc[mi][2 * j],     ah[mi], &bh[j][0]);
                    mma16816(acc[mi][2 * j + 1], ah[mi], &bh[j][2]);
                    mma16816(acc[mi][2 * j],     ah[mi], &bl[j][0]);
                    mma16816(acc[mi][2 * j + 1], ah[mi], &bl[j][2]);
                    mma16816(acc[mi][2 * j],     al[mi], &bh[j][0]);
                    mma16816(acc[mi][2 * j + 1], al[mi], &bh[j][2]);
                }
        }

        const int c0 = (cg * 4 + tile) * 128;
#pragma unroll
        for (int mi = 0; mi < 2; mi++)
#pragma unroll
            for (int nj = 0; nj < 8; nj++) {
                const int row = r0 + wm * 32 + mi * 16 + gid;
                const int col = c0 + wn * 64 + nj * 8 + t4 * 2;
                const float e00 = __expf(acc[mi][nj][0]);
                const float e01 = __expf(acc[mi][nj][1]);
                const float e10 = __expf(acc[mi][nj][2]);
                const float e11 = __expf(acc[mi][nj][3]);
                rowsum[mi][0] += e00 + e01;
                rowsum[mi][1] += e10 + e11;
                __nv_bfloat162 p0, p1;
                p0.x = __float2bfloat16(e00); p0.y = __float2bfloat16(e01);
                p1.x = __float2bfloat16(e10); p1.y = __float2bfloat16(e11);
                *(__nv_bfloat162*)&U[(size_t)row * NN + col] = p0;
                *(__nv_bfloat162*)&U[(size_t)(row + 8) * NN + col] = p1;
            }
        __syncthreads();
    }

#pragma unroll
    for (int mi = 0; mi < 2; mi++)
#pragma unroll
        for (int h = 0; h < 2; h++) {
            float v = rowsum[mi][h];
            v += __shfl_xor_sync(0xffffffffu, v, 1);
            v += __shfl_xor_sync(0xffffffffu, v, 2);
            if (t4 == 0) atomicAdd(&s_rs[wm * 32 + mi * 16 + gid + h * 8], v);
        }
    __syncthreads();
    if (tid < 128) g_rspart[(size_t)cg * BB * NN + b * NN + r0 + tid] = s_rs[tid];
}

// ---------------- invrs: reduce 8 rowsum partials ----------------
__global__ void invrs_kernel()
{
    const int i = blockIdx.x * 256 + threadIdx.x;   // over BB*NN
    float s = 0.f;
#pragma unroll
    for (int p = 0; p < 8; p++) s += g_rspart[(size_t)p * BB * NN + i];
    g_invrs[i] = 1.0f / s;
}

// ---------------- V' = V_fp32 * invrs[n] -> single bf16 plane ----------------
__global__ void vrescale_kernel()
{
    const int b = blockIdx.z;
    const size_t i4 = (size_t)blockIdx.x * 256 + threadIdx.x;   // over CC*NN/4
    const float4 v = ((const float4*)(g_V + (size_t)b * CC * NN))[i4];
    const int n4 = (int)((i4 * 4) & (NN - 1));
    const float4 w = *(const float4*)&g_invrs[b * NN + n4];
    __nv_bfloat162 p0, p1;
    p0.x = __float2bfloat16(v.x * w.x); p0.y = __float2bfloat16(v.y * w.y);
    p1.x = __float2bfloat16(v.z * w.z); p1.y = __float2bfloat16(v.w * w.w);
    uint2 o;
    o.x = *(uint32_t*)&p0; o.y = *(uint32_t*)&p1;
    ((uint2*)(g_Vhi + (size_t)b * CC * NN))[i4] = o;
}

// ---------------- weighted column sums (uint4 vectorized, invrs staged in smem) ----------------
__global__ void colsum_kernel()
{
    __shared__ float sw[128];
    const int b  = blockIdx.z;
    const int n0 = blockIdx.y * 128;
    const int m8 = blockIdx.x * 256 + threadIdx.x;   // uint4 index; covers 8 columns
    if (threadIdx.x < 128) sw[threadIdx.x] = g_invrs[b * NN + n0 + threadIdx.x];
    __syncthreads();

    const uint4* A4 = (const uint4*)(g_A + (size_t)b * NN * NN);
    float s[8];
#pragma unroll
    for (int j = 0; j < 8; j++) s[j] = 0.f;

#pragma unroll 4
    for (int n = 0; n < 128; n++) {
        const uint4 v = A4[(size_t)(n0 + n) * (NN / 8) + m8];
        const float w = sw[n];
        const __nv_bfloat162 p0 = *(const __nv_bfloat162*)&v.x;
        const __nv_bfloat162 p1 = *(const __nv_bfloat162*)&v.y;
        const __nv_bfloat162 p2 = *(const __nv_bfloat162*)&v.z;
        const __nv_bfloat162 p3 = *(const __nv_bfloat162*)&v.w;
        s[0] += w * __bfloat162float(p0.x);  s[1] += w * __bfloat162float(p0.y);
        s[2] += w * __bfloat162float(p1.x);  s[3] += w * __bfloat162float(p1.y);
        s[4] += w * __bfloat162float(p2.x);  s[5] += w * __bfloat162float(p2.y);
        s[6] += w * __bfloat162float(p3.x);  s[7] += w * __bfloat162float(p3.y);
    }
#pragma unroll
    for (int j = 0; j < 8; j++)
        atomicAdd(&g_colsum[b * NN + m8 * 8 + j], s[j]);
}

// ---------------- splits ----------------
__global__ void split4_kernel(const float* __restrict__ src, size_t srcBS,
                              __nv_bfloat16* __restrict__ hi, __nv_bfloat16* __restrict__ lo,
                              size_t dstBS)
{
    const size_t i4 = (size_t)blockIdx.x * 256 + threadIdx.x;
    const float4 v = ((const float4*)(src + (size_t)blockIdx.z * srcBS))[i4];
    __nv_bfloat162 ha, la, hb, lb;
    split_pack(v.x, v.y, ha, la);
    split_pack(v.z, v.w, hb, lb);
    uint2 hv, lv;
    hv.x = *(uint32_t*)&ha; hv.y = *(uint32_t*)&hb;
    lv.x = *(uint32_t*)&la; lv.y = *(uint32_t*)&lb;
    ((uint2*)(hi + (size_t)blockIdx.z * dstBS))[i4] = hv;
    ((uint2*)(lo + (size_t)blockIdx.z * dstBS))[i4] = lv;
}

__global__ void wqkv_split_kernel(const float* __restrict__ Wq, const float* __restrict__ Wk,
                                  const float* __restrict__ Wv)
{
    const int t = blockIdx.x * 256 + threadIdx.x;
    float v;
    if (t < 64 * CC) v = Wq[t];
    else if (t < 128 * CC) v = Wk[t - 64 * CC];
    else v = Wv[t - 128 * CC];
    __nv_bfloat16 h, l;
    split1(v, h, l);
    g_Wqkvhi[t] = h; g_Wqkvlo[t] = l;
}

// ---------------- misc ----------------
__global__ void zero_kernel()
{
    const int t = blockIdx.x * 256 + threadIdx.x;
    if (t < CC) { g_sum[t] = 0.f; g_sumsq[t] = 0.f; }
    if (t < BB * NN) g_colsum[t] = 0.f;
}

// final: inline BN (each block spans exactly one channel since NN = 2^12)
__global__ void final_kernel(const float* __restrict__ x,
                             const float* __restrict__ gamma, const float* __restrict__ beta,
                             float* __restrict__ out)
{
    const size_t idx = (size_t)blockIdx.x * 256 + threadIdx.x;
    const int c = (int)((idx >> 12) & (CC - 1));
    const float cnt = (float)(BB * NN);
    const float mean = g_sum[c] / cnt;
    const float var = g_sumsq[c] / cnt - mean * mean;
    const float sc = gamma[c] * rsqrtf(var + 1e-5f);
    const float sh = beta[c] - mean * sc;
    const float t = g_T[idx] * sc + sh;
    out[idx] = x[idx] + fmaxf(t, 0.f);
}

// ---------------- launch ----------------
extern "C" void kernel_launch(void* const* d_in, const int* in_sizes, int n_in,
                              void* d_out, int out_size)
{
    const float* x     = (const float*)d_in[0];
    const float* Wq    = (const float*)d_in[1];
    const float* Wk    = (const float*)d_in[2];
    const float* Wv    = (const float*)d_in[3];
    const float* bv    = (const float*)d_in[4];
    const float* Wt    = (const float*)d_in[5];
    const float* bt    = (const float*)d_in[6];
    const float* gamma = (const float*)d_in[7];
    const float* beta  = (const float*)d_in[8];
    float* out = (float*)d_out;

    float *pT;
    __nv_bfloat16 *pA, *pXhi, *pXlo, *pVhi, *pDhi, *pDlo;
    __nv_bfloat16 *pWqkvhi, *pWqkvlo, *pWthi, *pWtlo;
    cudaGetSymbolAddress((void**)&pT, g_T);
    cudaGetSymbolAddress((void**)&pA, g_A);
    cudaGetSymbolAddress((void**)&pXhi, g_xhi);
    cudaGetSymbolAddress((void**)&pXlo, g_xlo);
    cudaGetSymbolAddress((void**)&pVhi, g_Vhi);
    cudaGetSymbolAddress((void**)&pDhi, g_dhi);
    cudaGetSymbolAddress((void**)&pDlo, g_dlo);
    cudaGetSymbolAddress((void**)&pWqkvhi, g_Wqkvhi);
    cudaGetSymbolAddress((void**)&pWqkvlo, g_Wqkvlo);
    cudaGetSymbolAddress((void**)&pWthi, g_Wthi);
    cudaGetSymbolAddress((void**)&pWtlo, g_Wtlo);

    const int attn_smem = (2 * 128 * QA_ST + 2 * 2 * 64 * KB_ST) * 2 + 128 * 4;
    cudaFuncSetAttribute(attn_kernel, cudaFuncAttributeMaxDynamicSharedMemorySize, attn_smem);

    const int smem_22 = 4 * (2 * 128 * SA_STRIDE * 2 + 2 * 16 * SB_STRIDE * 2);  // 83968
    const int smem_11 = 4 * (1 * 128 * SA_STRIDE * 2 + 1 * 16 * SB_STRIDE * 2);  // 41984
    cudaFuncSetAttribute(mma_gemm_kernel<2, 2, 1>, cudaFuncAttributeMaxDynamicSharedMemorySize, smem_22);
    cudaFuncSetAttribute(mma_gemm_kernel<2, 2, 2>, cudaFuncAttributeMaxDynamicSharedMemorySize, smem_22);
    cudaFuncSetAttribute(mma_gemm_kernel<1, 1, 3>, cudaFuncAttributeMaxDynamicSharedMemorySize, smem_11);

    zero_kernel<<<BB * NN / 256, 256>>>();
    wqkv_split_kernel<<<384 * CC / 256, 256>>>(Wq, Wk, Wv);
    split4_kernel<<<dim3(CC * CC / 1024, 1, 1), 256>>>(Wt, 0, pWthi, pWtlo, 0);
    split4_kernel<<<dim3(CC * NN / 1024, 1, BB), 256>>>(x, (size_t)CC * NN, pXhi, pXlo, (size_t)CC * NN);

    // stacked QKV projection: [384,256] @ [256,4096]; epilogue writes Qt/K splits + V fp32
    mma_gemm_kernel<2, 2, 1><<<dim3(NN / 128, 3, BB), 256, smem_22>>>(
        pWqkvhi, pWqkvlo, CC, 0,
        pXhi, pXlo, (size_t)CC * NN,
        pT /*unused*/, 0, CC, bv, nullptr, 0);

    // fused energy + exp + rowsum -> U (bf16), rowsum partials (column-split grid)
    attn_kernel<<<dim3(8, NN / 128, BB), 256, attn_smem>>>();

    // invrs = 1 / sum of 8 partials
    invrs_kernel<<<BB * NN / 256, 256>>>();

    // V' = V_fp32 * invrs[n] -> single bf16 plane
    vrescale_kernel<<<dim3(CC * NN / 1024, 1, BB), 256>>>();

    // weighted column sums for L1 renorm (vectorized)
    colsum_kernel<<<dim3(NN / 2048, NN / 128, BB), 256>>>();

    // x_r = V' @ U (single-product); epilogue computes d = x - xr*colscale, writes d splits
    mma_gemm_kernel<1, 1, 3><<<dim3(NN / 128, CC / 128, BB), 256, smem_11>>>(
        pVhi, nullptr, NN, (size_t)CC * NN,
        pA, nullptr, (size_t)NN * NN,
        pT /*unused*/, 0, NN, nullptr, x, (size_t)CC * NN);

    // t = Wt @ d + bt, with BN stats -> g_T
    mma_gemm_kernel<2, 2, 2><<<dim3(NN / 128, CC / 128, BB), 256, smem_22>>>(
        pWthi, pWtlo, CC, 0,
        pDhi, pDlo, (size_t)CC * NN,
        pT, (size_t)CC * NN, CC, bt, nullptr, 0);

    // final with inline BN (replaces bn_finalize + old final)
    final_kernel<<<(size_t)BB * CC * NN / 256, 256>>>(x, gamma, beta, out);
}

// round 15
// speedup vs baseline: 1.0994x; 1.0331x over previous
#include <cuda_runtime.h>
#include <cuda_bf16.h>
#include <cstdint>

#define BB 4
#define CC 256
#define CQ 64
#define NN 4096

// ---------------- scratch (device globals; no allocations) ----------------
__device__ __nv_bfloat16 g_A[(size_t)BB * NN * NN];     // U = exp(E), bf16, unnormalized
__device__ __nv_bfloat16 g_xhi[(size_t)BB * CC * NN];
__device__ __nv_bfloat16 g_xlo[(size_t)BB * CC * NN];
__device__ float g_V[(size_t)BB * CC * NN];             // V fp32 (pre-rescale)
__device__ __nv_bfloat16 g_Vhi[(size_t)BB * CC * NN];   // V' = V*invrs, single bf16 plane
__device__ __nv_bfloat16 g_dhi[(size_t)BB * CC * NN];   // d = x - xr*colscale, split
__device__ __nv_bfloat16 g_dlo[(size_t)BB * CC * NN];
__device__ __nv_bfloat16 g_Qthi[(size_t)BB * NN * CQ];  // Q transposed [n][o]
__device__ __nv_bfloat16 g_Qtlo[(size_t)BB * NN * CQ];
__device__ __nv_bfloat16 g_Khi[(size_t)BB * CQ * NN];
__device__ __nv_bfloat16 g_Klo[(size_t)BB * CQ * NN];
__device__ __nv_bfloat16 g_Wqkvhi[384 * CC];            // Wq(64) ; Wk(64) ; Wv(256) rows
__device__ __nv_bfloat16 g_Wqkvlo[384 * CC];
__device__ __nv_bfloat16 g_Wthi[CC * CC];
__device__ __nv_bfloat16 g_Wtlo[CC * CC];
__device__ float g_T[(size_t)BB * CC * NN];
__device__ float g_rspart[8 * BB * NN];                 // per-colgroup rowsum partials
__device__ float g_invrs[BB * NN];                      // 1 / softmax row sums
__device__ float g_colsum[BB * NN];
__device__ float g_sum[CC];
__device__ float g_sumsq[CC];

// ---------------- PTX helpers ----------------
__device__ __forceinline__ void mma16816(float* c, const uint32_t* a, const uint32_t* b) {
    asm volatile(
        "mma.sync.aligned.m16n8k16.row.col.f32.bf16.bf16.f32 "
        "{%0,%1,%2,%3}, {%4,%5,%6,%7}, {%8,%9}, {%0,%1,%2,%3};\n"
        : "+f"(c[0]), "+f"(c[1]), "+f"(c[2]), "+f"(c[3])
        : "r"(a[0]), "r"(a[1]), "r"(a[2]), "r"(a[3]), "r"(b[0]), "r"(b[1]));
}
__device__ __forceinline__ void ldsm4(uint32_t* r, uint32_t addr) {
    asm volatile("ldmatrix.sync.aligned.m8n8.x4.shared.b16 {%0,%1,%2,%3}, [%4];"
        : "=r"(r[0]), "=r"(r[1]), "=r"(r[2]), "=r"(r[3]) : "r"(addr));
}
__device__ __forceinline__ void ldsm4t(uint32_t* r, uint32_t addr) {
    asm volatile("ldmatrix.sync.aligned.m8n8.x4.trans.shared.b16 {%0,%1,%2,%3}, [%4];"
        : "=r"(r[0]), "=r"(r[1]), "=r"(r[2]), "=r"(r[3]) : "r"(addr));
}
__device__ __forceinline__ void cpasync16(uint32_t saddr, const void* g) {
    asm volatile("cp.async.cg.shared.global [%0], [%1], 16;" :: "r"(saddr), "l"(g));
}
__device__ __forceinline__ void cp_commit() { asm volatile("cp.async.commit_group;" ::: "memory"); }

__device__ __forceinline__ void split1(float v, __nv_bfloat16& h, __nv_bfloat16& l) {
    h = __float2bfloat16(v);
    l = __float2bfloat16(v - __bfloat162float(h));
}
__device__ __forceinline__ void split_pack(float a, float b, __nv_bfloat162& hi2, __nv_bfloat162& lo2) {
    __nv_bfloat16 ha, la, hb, lb;
    split1(a, ha, la); split1(b, hb, lb);
    hi2.x = ha; hi2.y = hb;
    lo2.x = la; lo2.y = lb;
}

// ---------------- unified bf16-split tensor-core GEMM, 4-stage pipeline ----------------
// C[M,N] = (A0(+A1))[M,K] @ (B0(+B1))[K,N]     ldb = ldc = NN
// EPI 1 = stacked QKV projection epilogue (V stored fp32)
// EPI 2 = transform (+bias, BN stats)
// EPI 3 = xr->d: d = aux(x) - acc/(1e-9+colsum[col]), split store
#define SA_STRIDE 24
#define SB_STRIDE 136

template<int NA, int NB, int EPI>
__global__ __launch_bounds__(256)
void mma_gemm_kernel(const __nv_bfloat16* __restrict__ Ahi, const __nv_bfloat16* __restrict__ Alo,
                     int lda, size_t aBS,
                     const __nv_bfloat16* __restrict__ B0, const __nv_bfloat16* __restrict__ B1,
                     size_t bBS,
                     float* __restrict__ C, size_t cBS, int K,
                     const float* __restrict__ bias,
                     const float* __restrict__ aux, size_t auxBS)
{
    extern __shared__ __align__(16) char dynsm[];
    constexpr uint32_t A_PLANE = 128 * SA_STRIDE * 2;          // 6144
    constexpr uint32_t B_PLANE = 16 * SB_STRIDE * 2;           // 4352
    constexpr uint32_t STAGE   = NA * A_PLANE + NB * B_PLANE;

    const int bz = blockIdx.z;
    Ahi += (size_t)bz * aBS;
    if (NA == 2) Alo += (size_t)bz * aBS;
    B0  += (size_t)bz * bBS;
    if (NB == 2) B1 += (size_t)bz * bBS;
    C += (size_t)bz * cBS;
    if (EPI == 3) aux += (size_t)bz * auxBS;

    const int row0 = blockIdx.y * 128;
    const int col0 = blockIdx.x * 128;
    const int tid  = threadIdx.x;
    const int lane = tid & 31, warp = tid >> 5;
    const int wm = warp & 3;
    const int wn = warp >> 2;

    const int ar = tid >> 1, ac = (tid & 1) * 8;
    const int bk = tid >> 4, bc = (tid & 15) * 8;
    const size_t gA = (size_t)(row0 + ar) * lda + ac;
    const size_t gB = (size_t)bk * NN + col0 + bc;

    const uint32_t sbase = (uint32_t)__cvta_generic_to_shared(dynsm);
    const uint32_t sAst = (uint32_t)(ar * SA_STRIDE + ac) * 2;
    const uint32_t sBst = NA * A_PLANE + (uint32_t)(bk * SB_STRIDE + bc) * 2;

    float acc[2][8][4];
#pragma unroll
    for (int i = 0; i < 2; i++)
#pragma unroll
        for (int j = 0; j < 8; j++)
#pragma unroll
            for (int k = 0; k < 4; k++) acc[i][j][k] = 0.f;

    const int KT = K >> 4;

    auto issue = [&](int kt, int s) {
        const size_t ka = gA + (size_t)kt * 16;
        const size_t kb = gB + (size_t)kt * 16 * NN;
        const uint32_t st = sbase + (uint32_t)s * STAGE;
        cpasync16(st + sAst, Ahi + ka);
        if (NA == 2) cpasync16(st + A_PLANE + sAst, Alo + ka);
        cpasync16(st + sBst, B0 + kb);
        if (NB == 2) cpasync16(st + B_PLANE + sBst, B1 + kb);
    };

#pragma unroll
    for (int s = 0; s < 3; s++) { issue(s, s); cp_commit(); }

    const int lr = lane & 15, lc8 = (lane >> 4) * 8;
    const uint32_t aOff = ((wm * 32 + lr) * SA_STRIDE + lc8) * 2;
    const uint32_t bOff = NA * A_PLANE + (lr * SB_STRIDE + wn * 64 + lc8) * 2;

    for (int kt = 0; kt < KT; kt++) {
        asm volatile("cp.async.wait_group 2;" ::: "memory");
        __syncthreads();
        if (kt + 3 < KT) issue(kt + 3, (kt + 3) & 3);
        cp_commit();

        const uint32_t st = sbase + (uint32_t)(kt & 3) * STAGE;

        uint32_t ah[2][4], al[2][4];
#pragma unroll
        for (int mi = 0; mi < 2; mi++) {
            ldsm4(ah[mi], st + aOff + mi * 16 * SA_STRIDE * 2);
            if (NA == 2) ldsm4(al[mi], st + A_PLANE + aOff + mi * 16 * SA_STRIDE * 2);
        }
        uint32_t bh[4][4], bl[4][4];
#pragma unroll
        for (int j = 0; j < 4; j++) {
            ldsm4t(bh[j], st + bOff + j * 16 * 2);
            if (NB == 2) ldsm4t(bl[j], st + bOff + B_PLANE + j * 16 * 2);
        }
#pragma unroll
        for (int mi = 0; mi < 2; mi++) {
#pragma unroll
            for (int j = 0; j < 4; j++) {
                mma16816(acc[mi][2 * j],     ah[mi], &bh[j][0]);
                mma16816(acc[mi][2 * j + 1], ah[mi], &bh[j][2]);
                if (NB == 2) {
                    mma16816(acc[mi][2 * j],     ah[mi], &bl[j][0]);
                    mma16816(acc[mi][2 * j + 1], ah[mi], &bl[j][2]);
                }
                if (NA == 2) {
                    mma16816(acc[mi][2 * j],     al[mi], &bh[j][0]);
                    mma16816(acc[mi][2 * j + 1], al[mi], &bh[j][2]);
                }
            }
        }
    }

    const int gid = lane >> 2, t4 = lane & 3;

    if (EPI == 1) {
        const int by = blockIdx.y;
#pragma unroll
        for (int mi = 0; mi < 2; mi++)
#pragma unroll
            for (int nj = 0; nj < 8; nj++) {
                const int r = row0 + wm * 32 + mi * 16 + gid;
                const int col = col0 + wn * 64 + nj * 8 + t4 * 2;
                const float v00 = acc[mi][nj][0], v01 = acc[mi][nj][1];
                const float v10 = acc[mi][nj][2], v11 = acc[mi][nj][3];
                if (by == 0) {
                    if (r < 64) {  // Q -> transposed split [n][o]
                        const size_t base = (size_t)bz * NN * CQ;
                        __nv_bfloat16 h, l;
                        split1(v00, h, l); g_Qthi[base + (size_t)col * CQ + r] = h;       g_Qtlo[base + (size_t)col * CQ + r] = l;
                        split1(v01, h, l); g_Qthi[base + (size_t)(col + 1) * CQ + r] = h; g_Qtlo[base + (size_t)(col + 1) * CQ + r] = l;
                        split1(v10, h, l); g_Qthi[base + (size_t)col * CQ + r + 8] = h;       g_Qtlo[base + (size_t)col * CQ + r + 8] = l;
                        split1(v11, h, l); g_Qthi[base + (size_t)(col + 1) * CQ + r + 8] = h; g_Qtlo[base + (size_t)(col + 1) * CQ + r + 8] = l;
                    } else {       // K -> split [o][n]
                        const int kr = r - 64;
                        const size_t base = (size_t)bz * CQ * NN;
                        __nv_bfloat162 h2, l2;
                        split_pack(v00, v01, h2, l2);
                        *(__nv_bfloat162*)&g_Khi[base + (size_t)kr * NN + col] = h2;
                        *(__nv_bfloat162*)&g_Klo[base + (size_t)kr * NN + col] = l2;
                        split_pack(v10, v11, h2, l2);
                        *(__nv_bfloat162*)&g_Khi[base + (size_t)(kr + 8) * NN + col] = h2;
                        *(__nv_bfloat162*)&g_Klo[base + (size_t)(kr + 8) * NN + col] = l2;
                    }
                } else {           // V rows (+bias) -> fp32 (single rounding happens in vrescale)
                    const int vr = r - 128;
                    float* dst = g_V + (size_t)bz * CC * NN;
                    const float b0 = bias[vr], b1 = bias[vr + 8];
                    *(float2*)&dst[(size_t)vr * NN + col]       = make_float2(v00 + b0, v01 + b0);
                    *(float2*)&dst[(size_t)(vr + 8) * NN + col] = make_float2(v10 + b1, v11 + b1);
                }
            }
    }

    if (EPI == 2) {
        float ssum[2][2] = {{0.f, 0.f}, {0.f, 0.f}};
        float ssq[2][2]  = {{0.f, 0.f}, {0.f, 0.f}};
#pragma unroll
        for (int mi = 0; mi < 2; mi++)
#pragma unroll
            for (int nj = 0; nj < 8; nj++) {
                const int r = row0 + wm * 32 + mi * 16 + gid;
                const int col = col0 + wn * 64 + nj * 8 + t4 * 2;
                const float b0 = bias[r], b1 = bias[r + 8];
                const float v00 = acc[mi][nj][0] + b0, v01 = acc[mi][nj][1] + b0;
                const float v10 = acc[mi][nj][2] + b1, v11 = acc[mi][nj][3] + b1;
                *(float2*)&C[(size_t)r * NN + col]       = make_float2(v00, v01);
                *(float2*)&C[(size_t)(r + 8) * NN + col] = make_float2(v10, v11);
                ssum[mi][0] += v00 + v01;  ssq[mi][0] += v00 * v00 + v01 * v01;
                ssum[mi][1] += v10 + v11;  ssq[mi][1] += v10 * v10 + v11 * v11;
            }
#pragma unroll
        for (int mi = 0; mi < 2; mi++)
#pragma unroll
            for (int h = 0; h < 2; h++) {
                const int r = row0 + wm * 32 + mi * 16 + gid + h * 8;
                atomicAdd(&g_sum[r], ssum[mi][h]);
                atomicAdd(&g_sumsq[r], ssq[mi][h]);
            }
    }

    if (EPI == 3) {
#pragma unroll
        for (int mi = 0; mi < 2; mi++)
#pragma unroll
            for (int nj = 0; nj < 8; nj++) {
                const int r = row0 + wm * 32 + mi * 16 + gid;
                const int col = col0 + wn * 64 + nj * 8 + t4 * 2;
                const float cs0 = 1.0f / (1e-9f + g_colsum[bz * NN + col]);
                const float cs1 = 1.0f / (1e-9f + g_colsum[bz * NN + col + 1]);
                const size_t base = (size_t)bz * CC * NN;
                const float d00 = aux[(size_t)r * NN + col]       - acc[mi][nj][0] * cs0;
                const float d01 = aux[(size_t)r * NN + col + 1]   - acc[mi][nj][1] * cs1;
                const float d10 = aux[(size_t)(r + 8) * NN + col]     - acc[mi][nj][2] * cs0;
                const float d11 = aux[(size_t)(r + 8) * NN + col + 1] - acc[mi][nj][3] * cs1;
                __nv_bfloat162 h2, l2;
                split_pack(d00, d01, h2, l2);
                *(__nv_bfloat162*)&g_dhi[base + (size_t)r * NN + col] = h2;
                *(__nv_bfloat162*)&g_dlo[base + (size_t)r * NN + col] = l2;
                split_pack(d10, d11, h2, l2);
                *(__nv_bfloat162*)&g_dhi[base + (size_t)(r + 8) * NN + col] = h2;
                *(__nv_bfloat162*)&g_dlo[base + (size_t)(r + 8) * NN + col] = l2;
            }
    }
}

// ---------------- fused energy + exp + rowsum -> U bf16 ----------------
#define QA_ST 72
#define KB_ST 136

__global__ __launch_bounds__(256)
void attn_kernel()
{
    extern __shared__ __align__(16) char dsm[];
    __nv_bfloat16* sQ = (__nv_bfloat16*)dsm;
    __nv_bfloat16* sK = sQ + 2 * 128 * QA_ST;
    float* s_rs = (float*)(sK + 2 * 2 * 64 * KB_ST);

    const int cg = blockIdx.x;          // column group: 4 tiles of 128 = 512 cols
    const int b  = blockIdx.z;
    const int r0 = blockIdx.y * 128;
    const int tid = threadIdx.x;
    const int lane = tid & 31, warp = tid >> 5;
    const int wm = warp & 3, wn = warp >> 2;

    if (tid < 128) s_rs[tid] = 0.f;

    const uint32_t sQb = (uint32_t)__cvta_generic_to_shared(sQ);
    const uint32_t sKb = (uint32_t)__cvta_generic_to_shared(sK);

    const __nv_bfloat16* Qhi = g_Qthi + (size_t)b * NN * CQ;
    const __nv_bfloat16* Qlo = g_Qtlo + (size_t)b * NN * CQ;
#pragma unroll
    for (int p = 0; p < 4; p++) {
        const int idx = p * 256 + tid;
        const int row = idx >> 3, c8 = (idx & 7) * 8;
        cpasync16(sQb + (uint32_t)(row * QA_ST + c8) * 2,
                  Qhi + (size_t)(r0 + row) * CQ + c8);
        cpasync16(sQb + (uint32_t)(128 * QA_ST + row * QA_ST + c8) * 2,
                  Qlo + (size_t)(r0 + row) * CQ + c8);
    }
    cp_commit();

    const __nv_bfloat16* Khi = g_Khi + (size_t)b * CQ * NN;
    const __nv_bfloat16* Klo = g_Klo + (size_t)b * CQ * NN;
    const int kr = tid >> 4, kc8 = (tid & 15) * 8;

    auto issueK = [&](int tile, int stage) {
        const int c0 = (cg * 4 + tile) * 128;
        const uint32_t base = sKb + (uint32_t)stage * (2 * 64 * KB_ST * 2);
#pragma unroll
        for (int c = 0; c < 4; c++) {
            const int r = kr + c * 16;
            cpasync16(base + (uint32_t)(r * KB_ST + kc8) * 2,
                      Khi + (size_t)r * NN + c0 + kc8);
            cpasync16(base + (uint32_t)(64 * KB_ST + r * KB_ST + kc8) * 2,
                      Klo + (size_t)r * NN + c0 + kc8);
        }
        cp_commit();
    };

    issueK(0, 0);

    const int lr = lane & 15, lc8 = (lane >> 4) * 8;
    const uint32_t aBase = sQb + (uint32_t)((wm * 32 + lr) * QA_ST + lc8) * 2;
    const uint32_t bBase = sKb + (uint32_t)(lr * KB_ST + wn * 64 + lc8) * 2;
    constexpr uint32_t QPLANE = 128 * QA_ST * 2;
    constexpr uint32_t KPLANE = 64 * KB_ST * 2;
    constexpr uint32_t KSTAGE = 2 * KPLANE;

    const int gid = lane >> 2, t4 = lane & 3;
    float rowsum[2][2] = {{0.f, 0.f}, {0.f, 0.f}};
    __nv_bfloat16* U = g_A + (size_t)b * NN * NN;

    for (int tile = 0; tile < 4; tile++) {
        const int cur = tile & 1;
        if (tile + 1 < 4) {
            issueK(tile + 1, cur ^ 1);
            asm volatile("cp.async.wait_group 1;" ::: "memory");
        } else {
            asm volatile("cp.async.wait_group 0;" ::: "memory");
        }
        __syncthreads();

        const uint32_t bS = cur * KSTAGE;

        float acc[2][8][4];
#pragma unroll
        for (int i = 0; i < 2; i++)
#pragma unroll
            for (int j = 0; j < 8; j++)
#pragma unroll
                for (int k = 0; k < 4; k++) acc[i][j][k] = 0.f;

#pragma unroll
        for (int ch = 0; ch < 4; ch++) {
            uint32_t ah[2][4], al[2][4];
#pragma unroll
            for (int mi = 0; mi < 2; mi++) {
                ldsm4(ah[mi], aBase + ch * 32 + mi * 16 * QA_ST * 2);
                ldsm4(al[mi], aBase + QPLANE + ch * 32 + mi * 16 * QA_ST * 2);
            }
            uint32_t bh[4][4], bl[4][4];
#pragma unroll
            for (int j = 0; j < 4; j++) {
                ldsm4t(bh[j], bBase + bS + ch * 16 * KB_ST * 2 + j * 16 * 2);
                ldsm4t(bl[j], bBase + bS + KPLANE + ch * 16 * KB_ST * 2 + j * 16 * 2);
            }
#pragma unroll
            for (int mi = 0; mi < 2; mi++)
#pragma unroll
                for (int j = 0; j < 4; j++) {
                    mma16816(acc[mi][2 * j],     ah[mi], &bh[j][0]);
                    mma16816(acc[mi][2 * j + 1], ah[mi], &bh[j][2]);
                    mma16816(acc[mi][2 * j],     ah[mi], &bl[j][0]);
                    mma16816(acc[mi][2 * j + 1], ah[mi], &bl[j][2]);
                    mma16816(acc[mi][2 * j],     al[mi], &bh[j][0]);
                    mma16816(acc[mi][2 * j + 1], al[mi], &bh[j][2]);
                }
        }

        const int c0 = (cg * 4 + tile) * 128;
#pragma unroll
        for (int mi = 0; mi < 2; mi++)
#pragma unroll
            for (int nj = 0; nj < 8; nj++) {
                const int row = r0 + wm * 32 + mi * 16 + gid;
                const int col = c0 + wn * 64 + nj * 8 + t4 * 2;
                const float e00 = __expf(acc[mi][nj][0]);
                const float e01 = __expf(acc[mi][nj][1]);
                const float e10 = __expf(acc[mi][nj][2]);
                const float e11 = __expf(acc[mi][nj][3]);
                rowsum[mi][0] += e00 + e01;
                rowsum[mi][1] += e10 + e11;
                __nv_bfloat162 p0, p1;
                p0.x = __float2bfloat16(e00); p0.y = __float2bfloat16(e01);
                p1.x = __float2bfloat16(e10); p1.y = __float2bfloat16(e11);
                *(__nv_bfloat162*)&U[(size_t)row * NN + col] = p0;
                *(__nv_bfloat162*)&U[(size_t)(row + 8) * NN + col] = p1;
            }
        __syncthreads();
    }

#pragma unroll
    for (int mi = 0; mi < 2; mi++)
#pragma unroll
        for (int h = 0; h < 2; h++) {
            float v = rowsum[mi][h];
            v += __shfl_xor_sync(0xffffffffu, v, 1);
            v += __shfl_xor_sync(0xffffffffu, v, 2);
            if (t4 == 0) atomicAdd(&s_rs[wm * 32 + mi * 16 + gid + h * 8], v);
        }
    __syncthreads();
    if (tid < 128) g_rspart[(size_t)cg * BB * NN + b * NN + r0 + tid] = s_rs[tid];
}

// ---------------- invrs: reduce 8 rowsum partials ----------------
__global__ void invrs_kernel()
{
    const int i = blockIdx.x * 256 + threadIdx.x;   // over BB*NN
    float s = 0.f;
#pragma unroll
    for (int p = 0; p < 8; p++) s += g_rspart[(size_t)p * BB * NN + i];
    g_invrs[i] = 1.0f / s;
}

// ---------------- V' = V_fp32 * invrs[n] -> single bf16 plane ----------------
__global__ void vrescale_kernel()
{
    const int b = blockIdx.z;
    const size_t i4 = (size_t)blockIdx.x * 256 + threadIdx.x;   // over CC*NN/4
    const float4 v = ((const float4*)(g_V + (size_t)b * CC * NN))[i4];
    const int n4 = (int)((i4 * 4) & (NN - 1));
    const float4 w = *(const float4*)&g_invrs[b * NN + n4];
    __nv_bfloat162 p0, p1;
    p0.x = __float2bfloat16(v.x * w.x); p0.y = __float2bfloat16(v.y * w.y);
    p1.x = __float2bfloat16(v.z * w.z); p1.y = __float2bfloat16(v.w * w.w);
    uint2 o;
    o.x = *(uint32_t*)&p0; o.y = *(uint32_t*)&p1;
    ((uint2*)(g_Vhi + (size_t)b * CC * NN))[i4] = o;
}

// ---------------- weighted column sums (R10 version) ----------------
__global__ void colsum_kernel()
{
    const int m2 = blockIdx.x * 256 + threadIdx.x;
    const int b = blockIdx.z;
    const int n0 = blockIdx.y * 128;
    const __nv_bfloat162* A2 = (const __nv_bfloat162*)(g_A + (size_t)b * NN * NN);
    float s0 = 0.f, s1 = 0.f;
#pragma unroll 4
    for (int n = 0; n < 128; n++) {
        const float w = g_invrs[b * NN + n0 + n];
        const __nv_bfloat162 a = A2[(size_t)(n0 + n) * (NN / 2) + m2];
        s0 += __bfloat162float(a.x) * w;
        s1 += __bfloat162float(a.y) * w;
    }
    atomicAdd(&g_colsum[b * NN + 2 * m2 + 0], s0);
    atomicAdd(&g_colsum[b * NN + 2 * m2 + 1], s1);
}

// ---------------- splits ----------------
__global__ void split4_kernel(const float* __restrict__ src, size_t srcBS,
                              __nv_bfloat16* __restrict__ hi, __nv_bfloat16* __restrict__ lo,
                              size_t dstBS)
{
    const size_t i4 = (size_t)blockIdx.x * 256 + threadIdx.x;
    const float4 v = ((const float4*)(src + (size_t)blockIdx.z * srcBS))[i4];
    __nv_bfloat162 ha, la, hb, lb;
    split_pack(v.x, v.y, ha, la);
    split_pack(v.z, v.w, hb, lb);
    uint2 hv, lv;
    hv.x = *(uint32_t*)&ha; hv.y = *(uint32_t*)&hb;
    lv.x = *(uint32_t*)&la; lv.y = *(uint32_t*)&lb;
    ((uint2*)(hi + (size_t)blockIdx.z * dstBS))[i4] = hv;
    ((uint2*)(lo + (size_t)blockIdx.z * dstBS))[i4] = lv;
}

__global__ void wqkv_split_kernel(const float* __restrict__ Wq, const float* __restrict__ Wk,
                                  const float* __restrict__ Wv)
{
    const int t = blockIdx.x * 256 + threadIdx.x;
    float v;
    if (t < 64 * CC) v = Wq[t];
    else if (t < 128 * CC) v = Wk[t - 64 * CC];
    else v = Wv[t - 128 * CC];
    __nv_bfloat16 h, l;
    split1(v, h, l);
    g_Wqkvhi[t] = h; g_Wqkvlo[t] = l;
}

// ---------------- misc ----------------
__global__ void zero_kernel()
{
    const int t = blockIdx.x * 256 + threadIdx.x;
    if (t < CC) { g_sum[t] = 0.f; g_sumsq[t] = 0.f; }
    if (t < BB * NN) g_colsum[t] = 0.f;
}

// final: inline BN, computed ONCE per block (thread 0 -> shared broadcast).
// Each 256-thread block spans exactly one channel since 256 | 4096.
__global__ void final_kernel(const float* __restrict__ x,
                             const float* __restrict__ gamma, const float* __restrict__ beta,
                             float* __restrict__ out)
{
    __shared__ float s_sc, s_sh;
    const size_t idx = (size_t)blockIdx.x * 256 + threadIdx.x;
    if (threadIdx.x == 0) {
        const int c = (int)((idx >> 12) & (CC - 1));
        const float cnt = (float)(BB * NN);
        const float mean = g_sum[c] / cnt;
        const float var = g_sumsq[c] / cnt - mean * mean;
        const float sc = gamma[c] * rsqrtf(var + 1e-5f);
        s_sc = sc;
        s_sh = beta[c] - mean * sc;
    }
    __syncthreads();
    const float t = g_T[idx] * s_sc + s_sh;
    out[idx] = x[idx] + fmaxf(t, 0.f);
}

// ---------------- launch ----------------
extern "C" void kernel_launch(void* const* d_in, const int* in_sizes, int n_in,
                              void* d_out, int out_size)
{
    const float* x     = (const float*)d_in[0];
    const float* Wq    = (const float*)d_in[1];
    const float* Wk    = (const float*)d_in[2];
    const float* Wv    = (const float*)d_in[3];
    const float* bv    = (const float*)d_in[4];
    const float* Wt    = (const float*)d_in[5];
    const float* bt    = (const float*)d_in[6];
    const float* gamma = (const float*)d_in[7];
    const float* beta  = (const float*)d_in[8];
    float* out = (float*)d_out;

    float *pT;
    __nv_bfloat16 *pA, *pXhi, *pXlo, *pVhi, *pDhi, *pDlo;
    __nv_bfloat16 *pWqkvhi, *pWqkvlo, *pWthi, *pWtlo;
    cudaGetSymbolAddress((void**)&pT, g_T);
    cudaGetSymbolAddress((void**)&pA, g_A);
    cudaGetSymbolAddress((void**)&pXhi, g_xhi);
    cudaGetSymbolAddress((void**)&pXlo, g_xlo);
    cudaGetSymbolAddress((void**)&pVhi, g_Vhi);
    cudaGetSymbolAddress((void**)&pDhi, g_dhi);
    cudaGetSymbolAddress((void**)&pDlo, g_dlo);
    cudaGetSymbolAddress((void**)&pWqkvhi, g_Wqkvhi);
    cudaGetSymbolAddress((void**)&pWqkvlo, g_Wqkvlo);
    cudaGetSymbolAddress((void**)&pWthi, g_Wthi);
    cudaGetSymbolAddress((void**)&pWtlo, g_Wtlo);

    const int attn_smem = (2 * 128 * QA_ST + 2 * 2 * 64 * KB_ST) * 2 + 128 * 4;
    cudaFuncSetAttribute(attn_kernel, cudaFuncAttributeMaxDynamicSharedMemorySize, attn_smem);

    const int smem_22 = 4 * (2 * 128 * SA_STRIDE * 2 + 2 * 16 * SB_STRIDE * 2);  // 83968
    const int smem_11 = 4 * (1 * 128 * SA_STRIDE * 2 + 1 * 16 * SB_STRIDE * 2);  // 41984
    cudaFuncSetAttribute(mma_gemm_kernel<2, 2, 1>, cudaFuncAttributeMaxDynamicSharedMemorySize, smem_22);
    cudaFuncSetAttribute(mma_gemm_kernel<2, 2, 2>, cudaFuncAttributeMaxDynamicSharedMemorySize, smem_22);
    cudaFuncSetAttribute(mma_gemm_kernel<1, 1, 3>, cudaFuncAttributeMaxDynamicSharedMemorySize, smem_11);

    zero_kernel<<<BB * NN / 256, 256>>>();
    wqkv_split_kernel<<<384 * CC / 256, 256>>>(Wq, Wk, Wv);
    split4_kernel<<<dim3(CC * CC / 1024, 1, 1), 256>>>(Wt, 0, pWthi, pWtlo, 0);
    split4_kernel<<<dim3(CC * NN / 1024, 1, BB), 256>>>(x, (size_t)CC * NN, pXhi, pXlo, (size_t)CC * NN);

    // stacked QKV projection: [384,256] @ [256,4096]; epilogue writes Qt/K splits + V fp32
    mma_gemm_kernel<2, 2, 1><<<dim3(NN / 128, 3, BB), 256, smem_22>>>(
        pWqkvhi, pWqkvlo, CC, 0,
        pXhi, pXlo, (size_t)CC * NN,
        pT /*unused*/, 0, CC, bv, nullptr, 0);

    // fused energy + exp + rowsum -> U (bf16), rowsum partials (column-split grid)
    attn_kernel<<<dim3(8, NN / 128, BB), 256, attn_smem>>>();

    // invrs = 1 / sum of 8 partials
    invrs_kernel<<<BB * NN / 256, 256>>>();

    // V' = V_fp32 * invrs[n] -> single bf16 plane
    vrescale_kernel<<<dim3(CC * NN / 1024, 1, BB), 256>>>();

    // weighted column sums for L1 renorm
    colsum_kernel<<<dim3(NN / 512, NN / 128, BB), 256>>>();

    // x_r = V' @ U (single-product); epilogue computes d = x - xr*colscale, writes d splits
    mma_gemm_kernel<1, 1, 3><<<dim3(NN / 128, CC / 128, BB), 256, smem_11>>>(
        pVhi, nullptr, NN, (size_t)CC * NN,
        pA, nullptr, (size_t)NN * NN,
        pT /*unused*/, 0, NN, nullptr, x, (size_t)CC * NN);

    // t = Wt @ d + bt, with BN stats -> g_T
    mma_gemm_kernel<2, 2, 2><<<dim3(NN / 128, CC / 128, BB), 256, smem_22>>>(
        pWthi, pWtlo, CC, 0,
        pDhi, pDlo, (size_t)CC * NN,
        pT, (size_t)CC * NN, CC, bt, nullptr, 0);

    // final with per-block inline BN (replaces bn_finalize + old final)
    final_kernel<<<(size_t)BB * CC * NN / 256, 256>>>(x, gamma, beta, out);
}